// round 1
// baseline (speedup 1.0000x reference)
#include <cuda_runtime.h>
#include <math.h>
#include <stdint.h>

// Problem constants
#define BB 4
#define HH 128
#define WW 128
#define CC 768
#define WF 65            // WW/2 + 1
#define NB 8
#define BS 96
#define PI_D 3.14159265358979323846

// Spectrum scratch: [B, H, WF, C] planar real/imag. 25,559,040 floats each (~102MB).
#define NSPEC (BB * HH * WF * CC)
__device__ float g_Yr[NSPEC];
__device__ float g_Yi[NSPEC];

__device__ __forceinline__ float gelu_exact(float x) {
    return 0.5f * x * (1.0f + erff(x * 0.7071067811865476f));
}
__device__ __forceinline__ float sshrink(float v) {
    float a = fabsf(v) - 0.01f;
    return a > 0.0f ? copysignf(a, v) : 0.0f;
}

// ---------------------------------------------------------------------------
// K1: real DFT along W.  x[B,H,W,C] -> Y[B,H,WF,C] (complex planar)
// One block: one (b,h) row, 64 channels. Y[k][c] = sum_w x[w][c] * e^{-2pi i wk/128}
// ---------------------------------------------------------------------------
__global__ __launch_bounds__(256) void k_rfft_w(const float* __restrict__ x) {
    __shared__ float sx[128 * 64];
    __shared__ float2 tw[128];
    const int t = threadIdx.x;
    const int bh = blockIdx.x;          // 0..511  (b*H + h)
    const int cb = blockIdx.y * 64;

    const float* xp = x + (size_t)bh * WW * CC + cb;
    for (int idx = t; idx < 128 * 64; idx += 256) {
        int w = idx >> 6, c = idx & 63;
        sx[idx] = xp[(size_t)w * CC + c];
    }
    if (t < 128) {
        double a = -2.0 * PI_D * (double)t / 128.0;
        tw[t] = make_float2((float)cos(a), (float)sin(a));
    }
    __syncthreads();

    const int cl = t & 31;
    const int kq = t >> 5;              // 0..7
    float* yr = g_Yr + (size_t)bh * WF * CC + cb;
    float* yi = g_Yi + (size_t)bh * WF * CC + cb;

    for (int j = 0; j < 9; j++) {
        int k = kq + 8 * j;
        if (k > 64) break;
        float ar0 = 0.f, ai0 = 0.f, ar1 = 0.f, ai1 = 0.f;
        int ph = 0;
        #pragma unroll 4
        for (int w = 0; w < 128; w++) {
            float2 tt = tw[ph];
            float x0 = sx[(w << 6) + cl];
            float x1 = sx[(w << 6) + cl + 32];
            ar0 += x0 * tt.x; ai0 += x0 * tt.y;
            ar1 += x1 * tt.x; ai1 += x1 * tt.y;
            ph = (ph + k) & 127;
        }
        size_t o = (size_t)k * CC;
        yr[o + cl]      = ar0;  yi[o + cl]      = ai0;
        yr[o + cl + 32] = ar1;  yi[o + cl + 32] = ai1;
    }
}

// ---------------------------------------------------------------------------
// K2/K4: complex DFT along H, IN PLACE on g_Yr/g_Yi.
// One block owns a full 128-long H column for one (b, kw) and 64 channels.
// sgn = -1 forward (with scale 1/128), +1 inverse (scale 1).
// Radix-2 split: X[k] = E + O, X[k+64] = E - O  (E: even h, O: odd h)
// ---------------------------------------------------------------------------
__global__ __launch_bounds__(256) void k_fft_h(float sgn, float scale) {
    extern __shared__ float sm2[];
    float* syr = sm2;                    // 128*64
    float* syi = syr + 8192;             // 128*64
    float2* tw = (float2*)(syi + 8192);  // 128

    const int t = threadIdx.x;
    const int b  = blockIdx.x / WF;
    const int kw = blockIdx.x % WF;
    const int cb = blockIdx.y * 64;
    const size_t base = ((size_t)b * HH * WF + kw) * CC + cb;
    const size_t sh = (size_t)WF * CC;   // stride between h rows

    for (int idx = t; idx < 8192; idx += 256) {
        int h = idx >> 6, c = idx & 63;
        size_t g = base + (size_t)h * sh + c;
        syr[idx] = g_Yr[g];
        syi[idx] = g_Yi[g];
    }
    if (t < 128) {
        double a = 2.0 * PI_D * (double)t / 128.0;
        tw[t] = make_float2((float)cos(a), sgn * (float)sin(a));
    }
    __syncthreads();

    const int cl = t & 31;
    const int ko = t >> 5;               // 0..7
    for (int j = 0; j < 8; j++) {
        int k1 = ko + 8 * j;             // 0..63
        float er0 = 0.f, ei0 = 0.f, er1 = 0.f, ei1 = 0.f;
        float or0 = 0.f, oi0 = 0.f, or1 = 0.f, oi1 = 0.f;
        const int step = (2 * k1) & 127;
        int ph = 0;
        #pragma unroll 4
        for (int h = 0; h < 128; h += 2) {   // even h
            float2 tt = tw[ph];
            int s = h << 6;
            float yr0 = syr[s + cl],      yi0 = syi[s + cl];
            float yr1 = syr[s + cl + 32], yi1 = syi[s + cl + 32];
            er0 += yr0 * tt.x - yi0 * tt.y;  ei0 += yr0 * tt.y + yi0 * tt.x;
            er1 += yr1 * tt.x - yi1 * tt.y;  ei1 += yr1 * tt.y + yi1 * tt.x;
            ph = (ph + step) & 127;
        }
        ph = k1 & 127;
        #pragma unroll 4
        for (int h = 1; h < 128; h += 2) {   // odd h
            float2 tt = tw[ph];
            int s = h << 6;
            float yr0 = syr[s + cl],      yi0 = syi[s + cl];
            float yr1 = syr[s + cl + 32], yi1 = syi[s + cl + 32];
            or0 += yr0 * tt.x - yi0 * tt.y;  oi0 += yr0 * tt.y + yi0 * tt.x;
            or1 += yr1 * tt.x - yi1 * tt.y;  oi1 += yr1 * tt.y + yi1 * tt.x;
            ph = (ph + step) & 127;
        }
        size_t g1 = base + (size_t)k1 * sh;
        size_t g2 = base + (size_t)(k1 + 64) * sh;
        g_Yr[g1 + cl]      = (er0 + or0) * scale;  g_Yi[g1 + cl]      = (ei0 + oi0) * scale;
        g_Yr[g1 + cl + 32] = (er1 + or1) * scale;  g_Yi[g1 + cl + 32] = (ei1 + oi1) * scale;
        g_Yr[g2 + cl]      = (er0 - or0) * scale;  g_Yi[g2 + cl]      = (ei0 - oi0) * scale;
        g_Yr[g2 + cl + 32] = (er1 - or1) * scale;  g_Yi[g2 + cl + 32] = (ei1 - oi1) * scale;
    }
}

// ---------------------------------------------------------------------------
// K3: block-diagonal complex MLP, IN PLACE on g_Yr/g_Yi viewed as [M, C],
// M = B*H*WF = 33280. grid = (M/32, NB). Each block: 32 points x one 96-block.
// layer1: o1 = gelu(x @ (w1r + i w1i) + b1) ; layer2 + softshrink.
// ---------------------------------------------------------------------------
#define TM 32
__global__ __launch_bounds__(256) void k_mlp(const float* __restrict__ w1,
                                             const float* __restrict__ b1,
                                             const float* __restrict__ w2,
                                             const float* __restrict__ b2) {
    extern __shared__ float sm[];
    float* sw1r = sm;                  // 96*96
    float* sw1i = sw1r + 9216;
    float* sw2r = sw1i + 9216;
    float* sw2i = sw2r + 9216;
    float* sxr  = sw2i + 9216;         // 32*97 (padded)
    float* sxi  = sxr + 3104;
    float* so1r = sxi + 3104;          // 32*97
    float* so1i = so1r + 3104;
    float* sb   = so1i + 3104;         // 4*96: b1r, b1i, b2r, b2i

    const int t = threadIdx.x;
    const int n = blockIdx.y;
    const size_t pbase = (size_t)blockIdx.x * TM;
    const size_t wOff = (size_t)n * 9216;

    for (int idx = t; idx < 9216; idx += 256) {
        sw1r[idx] = w1[wOff + idx];
        sw1i[idx] = w1[(size_t)NB * 9216 + wOff + idx];
        sw2r[idx] = w2[wOff + idx];
        sw2i[idx] = w2[(size_t)NB * 9216 + wOff + idx];
    }
    if (t < 96) {
        sb[t]       = b1[n * 96 + t];
        sb[96 + t]  = b1[NB * 96 + n * 96 + t];
        sb[192 + t] = b2[n * 96 + t];
        sb[288 + t] = b2[NB * 96 + n * 96 + t];
    }
    for (int idx = t; idx < TM * 96; idx += 256) {
        int m = idx / 96, i = idx - m * 96;
        size_t g = (pbase + m) * CC + n * 96 + i;
        sxr[m * 97 + i] = g_Yr[g];
        sxi[m * 97 + i] = g_Yi[g];
    }
    __syncthreads();

    const int tx = t & 15, ty = t >> 4;
    const int o0 = tx * 6, m0 = ty * 2;

    // ---- layer 1 ----
    float a1r[2][6], a1i[2][6];
    #pragma unroll
    for (int mm = 0; mm < 2; mm++)
        #pragma unroll
        for (int u = 0; u < 6; u++) { a1r[mm][u] = 0.f; a1i[mm][u] = 0.f; }

    #pragma unroll 2
    for (int i = 0; i < 96; i++) {
        float x0r = sxr[m0 * 97 + i],       x0i = sxi[m0 * 97 + i];
        float x1r = sxr[(m0 + 1) * 97 + i], x1i = sxi[(m0 + 1) * 97 + i];
        #pragma unroll
        for (int u = 0; u < 6; u++) {
            float wr = sw1r[i * 96 + o0 + u];
            float wi = sw1i[i * 96 + o0 + u];
            a1r[0][u] += x0r * wr - x0i * wi;
            a1i[0][u] += x0i * wr + x0r * wi;
            a1r[1][u] += x1r * wr - x1i * wi;
            a1i[1][u] += x1i * wr + x1r * wi;
        }
    }
    #pragma unroll
    for (int mm = 0; mm < 2; mm++)
        #pragma unroll
        for (int u = 0; u < 6; u++) {
            float vr = a1r[mm][u] + sb[o0 + u];
            float vi = a1i[mm][u] + sb[96 + o0 + u];
            so1r[(m0 + mm) * 97 + o0 + u] = gelu_exact(vr);
            so1i[(m0 + mm) * 97 + o0 + u] = gelu_exact(vi);
        }
    __syncthreads();

    // ---- layer 2 ----
    float a2r[2][6], a2i[2][6];
    #pragma unroll
    for (int mm = 0; mm < 2; mm++)
        #pragma unroll
        for (int u = 0; u < 6; u++) { a2r[mm][u] = 0.f; a2i[mm][u] = 0.f; }

    #pragma unroll 2
    for (int i = 0; i < 96; i++) {
        float x0r = so1r[m0 * 97 + i],       x0i = so1i[m0 * 97 + i];
        float x1r = so1r[(m0 + 1) * 97 + i], x1i = so1i[(m0 + 1) * 97 + i];
        #pragma unroll
        for (int u = 0; u < 6; u++) {
            float wr = sw2r[i * 96 + o0 + u];
            float wi = sw2i[i * 96 + o0 + u];
            a2r[0][u] += x0r * wr - x0i * wi;
            a2i[0][u] += x0i * wr + x0r * wi;
            a2r[1][u] += x1r * wr - x1i * wi;
            a2i[1][u] += x1i * wr + x1r * wi;
        }
    }
    #pragma unroll
    for (int mm = 0; mm < 2; mm++)
        #pragma unroll
        for (int u = 0; u < 6; u++) {
            float vr = sshrink(a2r[mm][u] + sb[192 + o0 + u]);
            float vi = sshrink(a2i[mm][u] + sb[288 + o0 + u]);
            size_t g = (pbase + m0 + mm) * CC + n * 96 + o0 + u;
            g_Yr[g] = vr;
            g_Yi[g] = vi;
        }
}

// ---------------------------------------------------------------------------
// K5: inverse real DFT along W. Y[B,H,WF,C] -> out[B,H,W,C], scale 1/128.
// out[w] = (1/128) * ( Zr[0] + (-1)^w Zr[64] + 2*sum_{k=1..63}(Zr cos - Zi sin) )
// (Im of bins 0 and 64 contribute only imaginary parts -> dropped, matching irfft.)
// ---------------------------------------------------------------------------
__global__ __launch_bounds__(256) void k_irfft_w(float* __restrict__ out) {
    __shared__ float szr[65 * 64];
    __shared__ float szi[65 * 64];
    __shared__ float2 tw[128];
    const int t = threadIdx.x;
    const int bh = blockIdx.x;
    const int cb = blockIdx.y * 64;
    const size_t base = (size_t)bh * WF * CC + cb;

    for (int idx = t; idx < 65 * 64; idx += 256) {
        int k = idx >> 6, c = idx & 63;
        szr[idx] = g_Yr[base + (size_t)k * CC + c];
        szi[idx] = g_Yi[base + (size_t)k * CC + c];
    }
    if (t < 128) {
        double a = 2.0 * PI_D * (double)t / 128.0;
        tw[t] = make_float2((float)cos(a), (float)sin(a));
    }
    __syncthreads();

    const int cl = t & 31;
    const int wq = t >> 5;
    const float z0r0 = szr[cl],            z0r1 = szr[cl + 32];
    const float z64r0 = szr[(64 << 6) + cl], z64r1 = szr[(64 << 6) + cl + 32];
    const float inv = 1.0f / 128.0f;

    for (int j = 0; j < 8; j++) {
        int w1 = wq + 8 * j;             // 0..63
        float e0 = 0.f, e1 = 0.f, o0 = 0.f, o1 = 0.f;
        const int step = (2 * w1) & 127;
        int ph = (2 * w1) & 127;         // k = 2
        #pragma unroll 4
        for (int k = 2; k <= 62; k += 2) {
            float2 tt = tw[ph];
            int s = k << 6;
            e0 += szr[s + cl] * tt.x      - szi[s + cl] * tt.y;
            e1 += szr[s + cl + 32] * tt.x - szi[s + cl + 32] * tt.y;
            ph = (ph + step) & 127;
        }
        ph = w1 & 127;                   // k = 1
        #pragma unroll 4
        for (int k = 1; k <= 63; k += 2) {
            float2 tt = tw[ph];
            int s = k << 6;
            o0 += szr[s + cl] * tt.x      - szi[s + cl] * tt.y;
            o1 += szr[s + cl + 32] * tt.x - szi[s + cl + 32] * tt.y;
            ph = (ph + step) & 127;
        }
        float s64 = (w1 & 1) ? -1.f : 1.f;
        float base0 = z0r0 + s64 * z64r0;
        float base1 = z0r1 + s64 * z64r1;
        int w2 = w1 + 64;                // (-1)^{w2} == (-1)^{w1}
        size_t ob1 = ((size_t)bh * WW + w1) * CC + cb;
        size_t ob2 = ((size_t)bh * WW + w2) * CC + cb;
        out[ob1 + cl]      = (base0 + 2.f * (e0 + o0)) * inv;
        out[ob1 + cl + 32] = (base1 + 2.f * (e1 + o1)) * inv;
        out[ob2 + cl]      = (base0 + 2.f * (e0 - o0)) * inv;
        out[ob2 + cl + 32] = (base1 + 2.f * (e1 - o1)) * inv;
    }
}

// ---------------------------------------------------------------------------
extern "C" void kernel_launch(void* const* d_in, const int* in_sizes, int n_in,
                              void* d_out, int out_size) {
    const float* x  = (const float*)d_in[0];
    const float* w1 = (const float*)d_in[1];
    const float* b1 = (const float*)d_in[2];
    const float* w2 = (const float*)d_in[3];
    const float* b2 = (const float*)d_in[4];
    float* out = (float*)d_out;

    const int smem_ffth = (8192 * 2) * 4 + 128 * 8;                 // 66560
    const int smem_mlp  = (4 * 9216 + 4 * 3104 + 4 * 96) * 4;       // 198656
    cudaFuncSetAttribute(k_fft_h, cudaFuncAttributeMaxDynamicSharedMemorySize, smem_ffth);
    cudaFuncSetAttribute(k_mlp,   cudaFuncAttributeMaxDynamicSharedMemorySize, smem_mlp);

    dim3 g1(BB * HH, CC / 64);          // (512, 12)
    k_rfft_w<<<g1, 256>>>(x);

    dim3 g2(BB * WF, CC / 64);          // (260, 12)
    k_fft_h<<<g2, 256, smem_ffth>>>(-1.0f, 1.0f / 128.0f);   // forward, ortho fwd scale

    dim3 g3((BB * HH * WF) / TM, NB);   // (1040, 8)
    k_mlp<<<g3, 256, smem_mlp>>>(w1, b1, w2, b2);

    k_fft_h<<<g2, 256, smem_ffth>>>(+1.0f, 1.0f);            // inverse along H

    k_irfft_w<<<g1, 256>>>(out);        // inverse along W + ortho inv scale
}

// round 2
// speedup vs baseline: 1.2808x; 1.2808x over previous
#include <cuda_runtime.h>
#include <math.h>
#include <stdint.h>

#define BB 4
#define HH 128
#define WW 128
#define CC 768
#define WF 65            // WW/2 + 1
#define NB 8
#define PI_D 3.14159265358979323846

// Spectrum scratch, interleaved complex: [B, H, WF, C] float2 (~204MB)
#define NSPEC (BB * HH * WF * CC)
__device__ float2 g_Y[NSPEC];

__device__ __forceinline__ float gelu_exact(float x) {
    return 0.5f * x * (1.0f + erff(x * 0.7071067811865476f));
}
__device__ __forceinline__ float sshrink(float v) {
    float a = fabsf(v) - 0.01f;
    return a > 0.0f ? copysignf(a, v) : 0.0f;
}

// ---------------------------------------------------------------------------
// K1: real DFT along W.  x[B,H,W,C] -> Y[B,H,WF,C] (interleaved complex)
// Block: one (b,h) row, 128 channels. 4 k's x 4 channels per thread.
// ---------------------------------------------------------------------------
__global__ __launch_bounds__(256) void k_rfft_w(const float* __restrict__ x) {
    extern __shared__ float sm1[];
    float* sx = sm1;                       // 128 w * 128 c
    float2* tw = (float2*)(sx + 128 * 128);

    const int t = threadIdx.x;
    const int bh = blockIdx.x;             // 0..511
    const int cb = blockIdx.y * 128;

    const float* xp = x + (size_t)bh * WW * CC + cb;
    for (int v = t; v < 128 * 32; v += 256) {       // float4 loads
        int w = v >> 5, c4 = v & 31;
        float4 val = *(const float4*)(xp + (size_t)w * CC + c4 * 4);
        *(float4*)(sx + w * 128 + c4 * 4) = val;
    }
    if (t < 128) {
        double a = -2.0 * PI_D * (double)t / 128.0;
        tw[t] = make_float2((float)cos(a), (float)sin(a));
    }
    __syncthreads();

    const int cl = t & 31;
    const int kq = t >> 5;                 // 0..7
    float2* yout = g_Y + (size_t)bh * WF * CC + cb;

    for (int j = 0; j < 2; j++) {
        const int kb = kq + 8 * j;         // ks: kb, kb+16, kb+32, kb+48 (0..63)
        float ar[4][4], ai[4][4];
        #pragma unroll
        for (int q = 0; q < 4; q++)
            #pragma unroll
            for (int c = 0; c < 4; c++) { ar[q][c] = 0.f; ai[q][c] = 0.f; }
        int ph[4] = {0, 0, 0, 0};
        const int st[4] = {kb, kb + 16, kb + 32, kb + 48};

        #pragma unroll 2
        for (int w = 0; w < 128; w++) {
            float xv[4];
            #pragma unroll
            for (int c = 0; c < 4; c++) xv[c] = sx[w * 128 + cl + 32 * c];
            #pragma unroll
            for (int q = 0; q < 4; q++) {
                float2 tt = tw[ph[q]];
                #pragma unroll
                for (int c = 0; c < 4; c++) {
                    ar[q][c] += xv[c] * tt.x;
                    ai[q][c] += xv[c] * tt.y;
                }
                ph[q] = (ph[q] + st[q]) & 127;
            }
        }
        #pragma unroll
        for (int q = 0; q < 4; q++) {
            size_t o = (size_t)(kb + 16 * q) * CC;
            #pragma unroll
            for (int c = 0; c < 4; c++)
                yout[o + cl + 32 * c] = make_float2(ar[q][c], ai[q][c]);
        }
    }
    // k = 64: e^{-i pi w} = (-1)^w, purely real
    if (kq == 0) {
        float s[4] = {0.f, 0.f, 0.f, 0.f};
        #pragma unroll 4
        for (int w = 0; w < 128; w += 2) {
            #pragma unroll
            for (int c = 0; c < 4; c++)
                s[c] += sx[w * 128 + cl + 32 * c] - sx[(w + 1) * 128 + cl + 32 * c];
        }
        #pragma unroll
        for (int c = 0; c < 4; c++)
            yout[(size_t)64 * CC + cl + 32 * c] = make_float2(s[c], 0.f);
    }
}

// ---------------------------------------------------------------------------
// K2/K4: complex DFT along H, IN PLACE. Block: one (b,kw), 64 channels.
// Radix-2 even/odd split; 4 k's x 2 channels per thread.
// sgn=-1 fwd (scale 1/128), sgn=+1 inv (scale 1).
// ---------------------------------------------------------------------------
__global__ __launch_bounds__(256) void k_fft_h(float sgn, float scale) {
    extern __shared__ float sm2[];
    float2* sy = (float2*)sm2;             // 128 h * 64 c
    float2* tw = sy + 128 * 64;

    const int t = threadIdx.x;
    const int b  = blockIdx.x / WF;
    const int kw = blockIdx.x % WF;
    const int cb = blockIdx.y * 64;
    const size_t base = ((size_t)b * HH * WF + kw) * CC + cb;
    const size_t sh = (size_t)WF * CC;

    for (int idx = t; idx < 8192; idx += 256) {
        int h = idx >> 6, c = idx & 63;
        sy[idx] = g_Y[base + (size_t)h * sh + c];
    }
    if (t < 128) {
        double a = 2.0 * PI_D * (double)t / 128.0;
        tw[t] = make_float2((float)cos(a), sgn * (float)sin(a));
    }
    __syncthreads();

    const int cl = t & 31;
    const int kq = t >> 5;

    for (int j = 0; j < 2; j++) {
        const int kb = kq + 8 * j;         // k1s: kb+16q, q=0..3 (covers 0..63)
        float Er[4][2], Ei[4][2], Or[4][2], Oi[4][2];
        #pragma unroll
        for (int q = 0; q < 4; q++)
            #pragma unroll
            for (int c = 0; c < 2; c++) {
                Er[q][c] = Ei[q][c] = Or[q][c] = Oi[q][c] = 0.f;
            }
        const int st[4] = {(2 * kb) & 127, (2 * kb + 32) & 127,
                           (2 * kb + 64) & 127, (2 * kb + 96) & 127};
        int ph[4] = {0, 0, 0, 0};
        #pragma unroll 2
        for (int h = 0; h < 128; h += 2) {     // even h
            float2 y0 = sy[(h << 6) + cl];
            float2 y1 = sy[(h << 6) + cl + 32];
            #pragma unroll
            for (int q = 0; q < 4; q++) {
                float2 tt = tw[ph[q]];
                Er[q][0] += y0.x * tt.x - y0.y * tt.y;
                Ei[q][0] += y0.x * tt.y + y0.y * tt.x;
                Er[q][1] += y1.x * tt.x - y1.y * tt.y;
                Ei[q][1] += y1.x * tt.y + y1.y * tt.x;
                ph[q] = (ph[q] + st[q]) & 127;
            }
        }
        #pragma unroll
        for (int q = 0; q < 4; q++) ph[q] = (kb + 16 * q) & 127;
        #pragma unroll 2
        for (int h = 1; h < 128; h += 2) {     // odd h
            float2 y0 = sy[(h << 6) + cl];
            float2 y1 = sy[(h << 6) + cl + 32];
            #pragma unroll
            for (int q = 0; q < 4; q++) {
                float2 tt = tw[ph[q]];
                Or[q][0] += y0.x * tt.x - y0.y * tt.y;
                Oi[q][0] += y0.x * tt.y + y0.y * tt.x;
                Or[q][1] += y1.x * tt.x - y1.y * tt.y;
                Oi[q][1] += y1.x * tt.y + y1.y * tt.x;
                ph[q] = (ph[q] + st[q]) & 127;
            }
        }
        #pragma unroll
        for (int q = 0; q < 4; q++) {
            const int k1 = kb + 16 * q;
            size_t g1 = base + (size_t)k1 * sh;
            size_t g2 = base + (size_t)(k1 + 64) * sh;
            #pragma unroll
            for (int c = 0; c < 2; c++) {
                int cc = cl + 32 * c;
                g_Y[g1 + cc] = make_float2((Er[q][c] + Or[q][c]) * scale,
                                           (Ei[q][c] + Oi[q][c]) * scale);
                g_Y[g2 + cc] = make_float2((Er[q][c] - Or[q][c]) * scale,
                                           (Ei[q][c] - Oi[q][c]) * scale);
            }
        }
    }
}

// ---------------------------------------------------------------------------
// K3: block-diagonal complex MLP, IN PLACE. [M=33280 points, C].
// grid=(832, 8), block=320 (16 tx x 20 ty). TM=40 points, m-tile 2, o-tile 6.
// ---------------------------------------------------------------------------
#define TM 40
__global__ __launch_bounds__(320) void k_mlp(const float* __restrict__ w1,
                                             const float* __restrict__ b1,
                                             const float* __restrict__ w2,
                                             const float* __restrict__ b2) {
    extern __shared__ float sm[];
    float* sw1r = sm;                     // 96*96
    float* sw1i = sw1r + 9216;
    float* sw2r = sw1i + 9216;
    float* sw2i = sw2r + 9216;
    float2* sx  = (float2*)(sw2i + 9216); // 40*97
    float2* so1 = sx + TM * 97;           // 40*97
    float* sb   = (float*)(so1 + TM * 97);// 4*96

    const int t = threadIdx.x;
    const int n = blockIdx.y;
    const size_t pbase = (size_t)blockIdx.x * TM;
    const size_t wOff = (size_t)n * 9216;

    // weights via float4
    {
        const float4* w1r4 = (const float4*)(w1 + wOff);
        const float4* w1i4 = (const float4*)(w1 + (size_t)NB * 9216 + wOff);
        const float4* w2r4 = (const float4*)(w2 + wOff);
        const float4* w2i4 = (const float4*)(w2 + (size_t)NB * 9216 + wOff);
        for (int v = t; v < 2304; v += 320) {
            ((float4*)sw1r)[v] = w1r4[v];
            ((float4*)sw1i)[v] = w1i4[v];
            ((float4*)sw2r)[v] = w2r4[v];
            ((float4*)sw2i)[v] = w2i4[v];
        }
    }
    if (t < 96) {
        sb[t]       = b1[n * 96 + t];
        sb[96 + t]  = b1[NB * 96 + n * 96 + t];
        sb[192 + t] = b2[n * 96 + t];
        sb[288 + t] = b2[NB * 96 + n * 96 + t];
    }
    for (int idx = t; idx < TM * 96; idx += 320) {
        int m = idx / 96, i = idx - m * 96;
        sx[m * 97 + i] = g_Y[(pbase + m) * CC + n * 96 + i];
    }
    __syncthreads();

    const int tx = t & 15, ty = t >> 4;
    const int o0 = tx * 6, m0 = ty * 2;

    // ---- layer 1 ----
    {
        float a1r[2][6], a1i[2][6];
        #pragma unroll
        for (int mm = 0; mm < 2; mm++)
            #pragma unroll
            for (int u = 0; u < 6; u++) { a1r[mm][u] = 0.f; a1i[mm][u] = 0.f; }

        #pragma unroll 2
        for (int i = 0; i < 96; i++) {
            float2 x0 = sx[m0 * 97 + i];
            float2 x1 = sx[(m0 + 1) * 97 + i];
            float wr[6], wi[6];
            #pragma unroll
            for (int u = 0; u < 6; u++) {
                wr[u] = sw1r[i * 96 + o0 + u];
                wi[u] = sw1i[i * 96 + o0 + u];
            }
            #pragma unroll
            for (int u = 0; u < 6; u++) {
                a1r[0][u] += x0.x * wr[u] - x0.y * wi[u];
                a1i[0][u] += x0.y * wr[u] + x0.x * wi[u];
                a1r[1][u] += x1.x * wr[u] - x1.y * wi[u];
                a1i[1][u] += x1.y * wr[u] + x1.x * wi[u];
            }
        }
        #pragma unroll
        for (int mm = 0; mm < 2; mm++)
            #pragma unroll
            for (int u = 0; u < 6; u++) {
                float vr = a1r[mm][u] + sb[o0 + u];
                float vi = a1i[mm][u] + sb[96 + o0 + u];
                so1[(m0 + mm) * 97 + o0 + u] = make_float2(gelu_exact(vr), gelu_exact(vi));
            }
    }
    __syncthreads();

    // ---- layer 2 ----
    {
        float a2r[2][6], a2i[2][6];
        #pragma unroll
        for (int mm = 0; mm < 2; mm++)
            #pragma unroll
            for (int u = 0; u < 6; u++) { a2r[mm][u] = 0.f; a2i[mm][u] = 0.f; }

        #pragma unroll 2
        for (int i = 0; i < 96; i++) {
            float2 x0 = so1[m0 * 97 + i];
            float2 x1 = so1[(m0 + 1) * 97 + i];
            float wr[6], wi[6];
            #pragma unroll
            for (int u = 0; u < 6; u++) {
                wr[u] = sw2r[i * 96 + o0 + u];
                wi[u] = sw2i[i * 96 + o0 + u];
            }
            #pragma unroll
            for (int u = 0; u < 6; u++) {
                a2r[0][u] += x0.x * wr[u] - x0.y * wi[u];
                a2i[0][u] += x0.y * wr[u] + x0.x * wi[u];
                a2r[1][u] += x1.x * wr[u] - x1.y * wi[u];
                a2i[1][u] += x1.y * wr[u] + x1.x * wi[u];
            }
        }
        #pragma unroll
        for (int mm = 0; mm < 2; mm++)
            #pragma unroll
            for (int u = 0; u < 6; u++) {
                float vr = sshrink(a2r[mm][u] + sb[192 + o0 + u]);
                float vi = sshrink(a2i[mm][u] + sb[288 + o0 + u]);
                g_Y[(pbase + m0 + mm) * CC + n * 96 + o0 + u] = make_float2(vr, vi);
            }
    }
}

// ---------------------------------------------------------------------------
// K5: inverse real DFT along W. Block: one (b,h) row, 128 channels.
// 4 w's x 4 channels per thread, even/odd k split.
// ---------------------------------------------------------------------------
__global__ __launch_bounds__(256) void k_irfft_w(float* __restrict__ out) {
    extern __shared__ float sm5[];
    float2* sz = (float2*)sm5;             // 65 k * 128 c
    float2* tw = sz + 65 * 128;

    const int t = threadIdx.x;
    const int bh = blockIdx.x;
    const int cb = blockIdx.y * 128;
    const size_t base = (size_t)bh * WF * CC + cb;

    for (int idx = t; idx < 65 * 128; idx += 256) {
        int k = idx >> 7, c = idx & 127;
        sz[idx] = g_Y[base + (size_t)k * CC + c];
    }
    if (t < 128) {
        double a = 2.0 * PI_D * (double)t / 128.0;
        tw[t] = make_float2((float)cos(a), (float)sin(a));
    }
    __syncthreads();

    const int cl = t & 31;
    const int wq = t >> 5;
    const float inv = 1.0f / 128.0f;

    float z0r[4], z64r[4];
    #pragma unroll
    for (int c = 0; c < 4; c++) {
        z0r[c]  = sz[cl + 32 * c].x;
        z64r[c] = sz[(64 << 7) + cl + 32 * c].x;
    }

    for (int j = 0; j < 2; j++) {
        const int wb = wq + 8 * j;          // w1s: wb+16q (0..63)
        float ev[4][4], od[4][4];
        #pragma unroll
        for (int q = 0; q < 4; q++)
            #pragma unroll
            for (int c = 0; c < 4; c++) { ev[q][c] = 0.f; od[q][c] = 0.f; }
        const int st[4] = {(2 * wb) & 127, (2 * wb + 32) & 127,
                           (2 * wb + 64) & 127, (2 * wb + 96) & 127};
        int ph[4];
        #pragma unroll
        for (int q = 0; q < 4; q++) ph[q] = st[q];      // k=2 start
        #pragma unroll 2
        for (int k = 2; k <= 62; k += 2) {
            float2 zv[4];
            #pragma unroll
            for (int c = 0; c < 4; c++) zv[c] = sz[(k << 7) + cl + 32 * c];
            #pragma unroll
            for (int q = 0; q < 4; q++) {
                float2 tt = tw[ph[q]];
                #pragma unroll
                for (int c = 0; c < 4; c++)
                    ev[q][c] += zv[c].x * tt.x - zv[c].y * tt.y;
                ph[q] = (ph[q] + st[q]) & 127;
            }
        }
        #pragma unroll
        for (int q = 0; q < 4; q++) ph[q] = (wb + 16 * q) & 127;  // k=1 start
        #pragma unroll 2
        for (int k = 1; k <= 63; k += 2) {
            float2 zv[4];
            #pragma unroll
            for (int c = 0; c < 4; c++) zv[c] = sz[(k << 7) + cl + 32 * c];
            #pragma unroll
            for (int q = 0; q < 4; q++) {
                float2 tt = tw[ph[q]];
                #pragma unroll
                for (int c = 0; c < 4; c++)
                    od[q][c] += zv[c].x * tt.x - zv[c].y * tt.y;
                ph[q] = (ph[q] + st[q]) & 127;
            }
        }
        const float s64 = (wb & 1) ? -1.f : 1.f;        // parity of w1 = parity of wb
        #pragma unroll
        for (int q = 0; q < 4; q++) {
            const int w1 = wb + 16 * q;
            const int w2 = w1 + 64;
            size_t ob1 = ((size_t)bh * WW + w1) * CC + cb;
            size_t ob2 = ((size_t)bh * WW + w2) * CC + cb;
            #pragma unroll
            for (int c = 0; c < 4; c++) {
                float b0 = z0r[c] + s64 * z64r[c];
                out[ob1 + cl + 32 * c] = (b0 + 2.f * (ev[q][c] + od[q][c])) * inv;
                out[ob2 + cl + 32 * c] = (b0 + 2.f * (ev[q][c] - od[q][c])) * inv;
            }
        }
    }
}

// ---------------------------------------------------------------------------
extern "C" void kernel_launch(void* const* d_in, const int* in_sizes, int n_in,
                              void* d_out, int out_size) {
    const float* x  = (const float*)d_in[0];
    const float* w1 = (const float*)d_in[1];
    const float* b1 = (const float*)d_in[2];
    const float* w2 = (const float*)d_in[3];
    const float* b2 = (const float*)d_in[4];
    float* out = (float*)d_out;

    const int smem_rfft  = 128 * 128 * 4 + 128 * 8;                  // 66560
    const int smem_ffth  = 128 * 64 * 8 + 128 * 8;                   // 66560
    const int smem_mlp   = 4 * 9216 * 4 + 2 * TM * 97 * 8 + 384 * 4; // 211072
    const int smem_irfft = 65 * 128 * 8 + 128 * 8;                   // 67584
    cudaFuncSetAttribute(k_rfft_w, cudaFuncAttributeMaxDynamicSharedMemorySize, smem_rfft);
    cudaFuncSetAttribute(k_fft_h,  cudaFuncAttributeMaxDynamicSharedMemorySize, smem_ffth);
    cudaFuncSetAttribute(k_mlp,    cudaFuncAttributeMaxDynamicSharedMemorySize, smem_mlp);
    cudaFuncSetAttribute(k_irfft_w, cudaFuncAttributeMaxDynamicSharedMemorySize, smem_irfft);

    dim3 g1(BB * HH, CC / 128);          // (512, 6)
    k_rfft_w<<<g1, 256, smem_rfft>>>(x);

    dim3 g2(BB * WF, CC / 64);           // (260, 12)
    k_fft_h<<<g2, 256, smem_ffth>>>(-1.0f, 1.0f / 128.0f);

    dim3 g3((BB * HH * WF) / TM, NB);    // (832, 8)
    k_mlp<<<g3, 320, smem_mlp>>>(w1, b1, w2, b2);

    k_fft_h<<<g2, 256, smem_ffth>>>(+1.0f, 1.0f);

    k_irfft_w<<<g1, 256, smem_irfft>>>(out);
}

// round 3
// speedup vs baseline: 1.6848x; 1.3154x over previous
#include <cuda_runtime.h>
#include <math.h>
#include <stdint.h>

#define BB 4
#define HH 128
#define WW 128
#define CC 768
#define WF 65            // WW/2 + 1
#define NB 8
#define PI_D 3.14159265358979323846

// Spectrum scratch, interleaved complex: [B, H, WF, C] float2 (~204MB)
#define NSPEC (BB * HH * WF * CC)
__device__ float2 g_Y[NSPEC];

__device__ __forceinline__ float gelu_exact(float x) {
    return 0.5f * x * (1.0f + erff(x * 0.7071067811865476f));
}
__device__ __forceinline__ float sshrink(float v) {
    float a = fabsf(v) - 0.01f;
    return a > 0.0f ? copysignf(a, v) : 0.0f;
}

// ===========================================================================
// K1: real FFT along W (four-step: w = 8*w1 + w0).
// Block: one (b,h) row, 64 channels. Stage A: 16-pt real-input DFT per w0
// class (conj-symmetric, store k0=0..7 complex in-place + real k0=8 side).
// Stage B: Y[k] = sum_{w0} e^{-2pi i w0 k/128} G[w0][k mod 16].
// ===========================================================================
__global__ __launch_bounds__(256) void k_rfft_w(const float* __restrict__ x) {
    extern __shared__ float sm1[];
    float* sx = sm1;                         // 128 w * 64 c floats
    float* sg8 = sx + 8192;                  // 8 w0 * 64 c (real G[.,8])
    float2* tw = (float2*)(sg8 + 512);       // 128: e^{-2pi i j/128}
    float2* tw16 = tw + 128;                 // 16:  e^{-2pi i j/16}

    const int t = threadIdx.x;
    const int bh = blockIdx.x;
    const int cb = blockIdx.y * 64;

    const float* xp = x + (size_t)bh * WW * CC + cb;
    for (int v = t; v < 128 * 16; v += 256) {
        int w = v >> 4, c4 = v & 15;
        ((float4*)(sx + w * 64))[c4] = ((const float4*)(xp + (size_t)w * CC))[c4];
    }
    if (t < 128) {
        double a = -2.0 * PI_D * (double)t / 128.0;
        tw[t] = make_float2((float)cos(a), (float)sin(a));
    }
    if (t < 16) {
        double a = -2.0 * PI_D * (double)t / 16.0;
        tw16[t] = make_float2((float)cos(a), (float)sin(a));
    }
    __syncthreads();

    const int cl = t & 31;
    const int w0 = t >> 5;                   // 0..7

    // ---- Stage A ----
    #pragma unroll
    for (int cc = 0; cc < 2; cc++) {
        const int ch = cl + 32 * cc;
        float xv[16];
        #pragma unroll
        for (int w1 = 0; w1 < 16; w1++) xv[w1] = sx[((w1 << 3) + w0) * 64 + ch];
        #pragma unroll
        for (int m = 0; m < 8; m++) {
            float2 E = make_float2(0.f, 0.f), O = make_float2(0.f, 0.f);
            int ph = 0; const int st = (2 * m) & 15;
            #pragma unroll
            for (int u = 0; u < 8; u++) {
                float2 tt = tw16[ph];
                E.x += xv[2 * u] * tt.x;     E.y += xv[2 * u] * tt.y;
                O.x += xv[2 * u + 1] * tt.x; O.y += xv[2 * u + 1] * tt.y;
                ph = (ph + st) & 15;
            }
            if (m == 0) sg8[w0 * 64 + ch] = E.x - O.x;   // G[w0][8] (real)
            float2 wm = tw16[m];
            float wOx = wm.x * O.x - wm.y * O.y;
            float wOy = wm.x * O.y + wm.y * O.x;
            sx[((m << 3) + w0) * 64 + ch]       = E.x + wOx;   // Re G[w0][m]
            sx[(((m + 8) << 3) + w0) * 64 + ch] = E.y + wOy;   // Im G[w0][m]
        }
    }
    __syncthreads();

    // ---- Stage B ----
    const int kq = w0;
    float2* yout = g_Y + (size_t)bh * WF * CC + cb;
    const int jmax = (kq == 0) ? 9 : 8;
    for (int j = 0; j < jmax; j++) {
        const int k = kq + 8 * j;            // 0..63, plus 64 for kq==0
        const int k0 = k & 15;
        const bool is8 = (k0 == 8);
        const int k0p = (k0 <= 8) ? k0 : 16 - k0;
        const float si = (k0 <= 8) ? 1.f : -1.f;
        #pragma unroll
        for (int cc = 0; cc < 2; cc++) {
            const int ch = cl + 32 * cc;
            float ax = 0.f, ay = 0.f;
            int ph = 0;
            #pragma unroll
            for (int p = 0; p < 8; p++) {
                float2 tt = tw[ph];
                float gre, gim;
                if (is8) { gre = sg8[p * 64 + ch]; gim = 0.f; }
                else {
                    gre = sx[((k0p << 3) + p) * 64 + ch];
                    gim = si * sx[(((k0p + 8) << 3) + p) * 64 + ch];
                }
                ax += gre * tt.x - gim * tt.y;
                ay += gre * tt.y + gim * tt.x;
                ph = (ph + k) & 127;
            }
            yout[(size_t)k * CC + ch] = make_float2(ax, ay);
        }
    }
}

// ===========================================================================
// K2/K4: complex FFT along H (four-step), IN PLACE. Block: one (b,kw), 64 ch.
// sgn=-1 fwd (scale 1/128), sgn=+1 inv (scale 1).
// ===========================================================================
__global__ __launch_bounds__(256) void k_fft_h(float sgn, float scale) {
    extern __shared__ float sm2[];
    float2* sy = (float2*)sm2;               // 128 h * 64 c
    float2* tw = sy + 8192;                  // 128
    float2* tw16 = tw + 128;                 // 16

    const int t = threadIdx.x;
    const int b  = blockIdx.x / WF;
    const int kw = blockIdx.x % WF;
    const int cb = blockIdx.y * 64;
    const size_t base = ((size_t)b * HH * WF + kw) * CC + cb;
    const size_t sh = (size_t)WF * CC;

    for (int idx = t; idx < 8192; idx += 256) {
        int h = idx >> 6, c = idx & 63;
        sy[idx] = g_Y[base + (size_t)h * sh + c];
    }
    if (t < 128) {
        double a = sgn * 2.0 * PI_D * (double)t / 128.0;
        tw[t] = make_float2((float)cos(a), (float)sin(a));
    }
    if (t < 16) {
        double a = sgn * 2.0 * PI_D * (double)t / 16.0;
        tw16[t] = make_float2((float)cos(a), (float)sin(a));
    }
    __syncthreads();

    const int cl = t & 31;
    const int h0 = t >> 5;                   // 0..7

    // ---- Stage A: 16-pt DFT over h1 (radix-2), in place ----
    #pragma unroll
    for (int cc = 0; cc < 2; cc++) {
        const int ch = cl + 32 * cc;
        float2 yv[16];
        #pragma unroll
        for (int h1 = 0; h1 < 16; h1++) yv[h1] = sy[((h1 << 3) + h0) * 64 + ch];
        #pragma unroll
        for (int m = 0; m < 8; m++) {
            float2 E = make_float2(0.f, 0.f), O = make_float2(0.f, 0.f);
            int ph = 0; const int st = (2 * m) & 15;
            #pragma unroll
            for (int u = 0; u < 8; u++) {
                float2 tt = tw16[ph];
                float2 a = yv[2 * u], bv = yv[2 * u + 1];
                E.x += a.x * tt.x - a.y * tt.y;   E.y += a.x * tt.y + a.y * tt.x;
                O.x += bv.x * tt.x - bv.y * tt.y; O.y += bv.x * tt.y + bv.y * tt.x;
                ph = (ph + st) & 15;
            }
            float2 wm = tw16[m];
            float wOx = wm.x * O.x - wm.y * O.y;
            float wOy = wm.x * O.y + wm.y * O.x;
            sy[((m << 3) + h0) * 64 + ch]       = make_float2(E.x + wOx, E.y + wOy);
            sy[(((m + 8) << 3) + h0) * 64 + ch] = make_float2(E.x - wOx, E.y - wOy);
        }
    }
    __syncthreads();

    // ---- Stage B: X[k] = sum_{p} tw[p*k] G[p][k mod 16], pairs (k, k+64) ----
    const int kq = h0;
    #pragma unroll
    for (int j = 0; j < 8; j++) {
        const int k = kq + 8 * j;            // 0..63
        const int k0 = k & 15;
        #pragma unroll
        for (int cc = 0; cc < 2; cc++) {
            const int ch = cl + 32 * cc;
            float Ex = 0.f, Ey = 0.f, Ox = 0.f, Oy = 0.f;
            int ph = 0;
            #pragma unroll
            for (int p = 0; p < 8; p++) {
                float2 tt = tw[ph];
                float2 g = sy[((k0 << 3) + p) * 64 + ch];
                float rx = g.x * tt.x - g.y * tt.y;
                float ry = g.x * tt.y + g.y * tt.x;
                if ((p & 1) == 0) { Ex += rx; Ey += ry; }
                else              { Ox += rx; Oy += ry; }
                ph = (ph + k) & 127;
            }
            g_Y[base + (size_t)k * sh + ch] =
                make_float2((Ex + Ox) * scale, (Ey + Oy) * scale);
            g_Y[base + (size_t)(k + 64) * sh + ch] =
                make_float2((Ex - Ox) * scale, (Ey - Oy) * scale);
        }
    }
}

// ===========================================================================
// K3: block-diagonal complex MLP, IN PLACE (unchanged from R2).
// ===========================================================================
#define TM 40
__global__ __launch_bounds__(320) void k_mlp(const float* __restrict__ w1,
                                             const float* __restrict__ b1,
                                             const float* __restrict__ w2,
                                             const float* __restrict__ b2) {
    extern __shared__ float sm[];
    float* sw1r = sm;                     // 96*96
    float* sw1i = sw1r + 9216;
    float* sw2r = sw1i + 9216;
    float* sw2i = sw2r + 9216;
    float2* sx  = (float2*)(sw2i + 9216); // 40*97
    float2* so1 = sx + TM * 97;           // 40*97
    float* sb   = (float*)(so1 + TM * 97);// 4*96

    const int t = threadIdx.x;
    const int n = blockIdx.y;
    const size_t pbase = (size_t)blockIdx.x * TM;
    const size_t wOff = (size_t)n * 9216;

    {
        const float4* w1r4 = (const float4*)(w1 + wOff);
        const float4* w1i4 = (const float4*)(w1 + (size_t)NB * 9216 + wOff);
        const float4* w2r4 = (const float4*)(w2 + wOff);
        const float4* w2i4 = (const float4*)(w2 + (size_t)NB * 9216 + wOff);
        for (int v = t; v < 2304; v += 320) {
            ((float4*)sw1r)[v] = w1r4[v];
            ((float4*)sw1i)[v] = w1i4[v];
            ((float4*)sw2r)[v] = w2r4[v];
            ((float4*)sw2i)[v] = w2i4[v];
        }
    }
    if (t < 96) {
        sb[t]       = b1[n * 96 + t];
        sb[96 + t]  = b1[NB * 96 + n * 96 + t];
        sb[192 + t] = b2[n * 96 + t];
        sb[288 + t] = b2[NB * 96 + n * 96 + t];
    }
    for (int idx = t; idx < TM * 96; idx += 320) {
        int m = idx / 96, i = idx - m * 96;
        sx[m * 97 + i] = g_Y[(pbase + m) * CC + n * 96 + i];
    }
    __syncthreads();

    const int tx = t & 15, ty = t >> 4;
    const int o0 = tx * 6, m0 = ty * 2;

    {
        float a1r[2][6], a1i[2][6];
        #pragma unroll
        for (int mm = 0; mm < 2; mm++)
            #pragma unroll
            for (int u = 0; u < 6; u++) { a1r[mm][u] = 0.f; a1i[mm][u] = 0.f; }

        #pragma unroll 2
        for (int i = 0; i < 96; i++) {
            float2 x0 = sx[m0 * 97 + i];
            float2 x1 = sx[(m0 + 1) * 97 + i];
            float wr[6], wi[6];
            #pragma unroll
            for (int u = 0; u < 6; u++) {
                wr[u] = sw1r[i * 96 + o0 + u];
                wi[u] = sw1i[i * 96 + o0 + u];
            }
            #pragma unroll
            for (int u = 0; u < 6; u++) {
                a1r[0][u] += x0.x * wr[u] - x0.y * wi[u];
                a1i[0][u] += x0.y * wr[u] + x0.x * wi[u];
                a1r[1][u] += x1.x * wr[u] - x1.y * wi[u];
                a1i[1][u] += x1.y * wr[u] + x1.x * wi[u];
            }
        }
        #pragma unroll
        for (int mm = 0; mm < 2; mm++)
            #pragma unroll
            for (int u = 0; u < 6; u++) {
                float vr = a1r[mm][u] + sb[o0 + u];
                float vi = a1i[mm][u] + sb[96 + o0 + u];
                so1[(m0 + mm) * 97 + o0 + u] = make_float2(gelu_exact(vr), gelu_exact(vi));
            }
    }
    __syncthreads();

    {
        float a2r[2][6], a2i[2][6];
        #pragma unroll
        for (int mm = 0; mm < 2; mm++)
            #pragma unroll
            for (int u = 0; u < 6; u++) { a2r[mm][u] = 0.f; a2i[mm][u] = 0.f; }

        #pragma unroll 2
        for (int i = 0; i < 96; i++) {
            float2 x0 = so1[m0 * 97 + i];
            float2 x1 = so1[(m0 + 1) * 97 + i];
            float wr[6], wi[6];
            #pragma unroll
            for (int u = 0; u < 6; u++) {
                wr[u] = sw2r[i * 96 + o0 + u];
                wi[u] = sw2i[i * 96 + o0 + u];
            }
            #pragma unroll
            for (int u = 0; u < 6; u++) {
                a2r[0][u] += x0.x * wr[u] - x0.y * wi[u];
                a2i[0][u] += x0.y * wr[u] + x0.x * wi[u];
                a2r[1][u] += x1.x * wr[u] - x1.y * wi[u];
                a2i[1][u] += x1.y * wr[u] + x1.x * wi[u];
            }
        }
        #pragma unroll
        for (int mm = 0; mm < 2; mm++)
            #pragma unroll
            for (int u = 0; u < 6; u++) {
                float vr = sshrink(a2r[mm][u] + sb[192 + o0 + u]);
                float vi = sshrink(a2i[mm][u] + sb[288 + o0 + u]);
                g_Y[(pbase + m0 + mm) * CC + n * 96 + o0 + u] = make_float2(vr, vi);
            }
    }
}

// ===========================================================================
// K5: inverse real FFT along W (four-step). Block: one (b,h) row, 64 ch.
// Hermitian-extend on load; Stage A = complex 16-pt (sgn=+1); Stage B takes
// real part only (2 FMA per term), pairs (w, w+64).
// ===========================================================================
__global__ __launch_bounds__(256) void k_irfft_w(float* __restrict__ out) {
    extern __shared__ float sm5[];
    float2* sz = (float2*)sm5;               // 128 k * 64 c
    float2* tw = sz + 8192;                  // 128: e^{+2pi i j/128}
    float2* tw16 = tw + 128;                 // 16

    const int t = threadIdx.x;
    const int bh = blockIdx.x;
    const int cb = blockIdx.y * 64;
    const size_t base = (size_t)bh * WF * CC + cb;

    for (int idx = t; idx < 8192; idx += 256) {
        int k = idx >> 6, c = idx & 63;
        if (k <= 64) {
            sz[idx] = g_Y[base + (size_t)k * CC + c];
        } else {
            float2 v = g_Y[base + (size_t)(128 - k) * CC + c];
            sz[idx] = make_float2(v.x, -v.y);
        }
    }
    if (t < 128) {
        double a = 2.0 * PI_D * (double)t / 128.0;
        tw[t] = make_float2((float)cos(a), (float)sin(a));
    }
    if (t < 16) {
        double a = 2.0 * PI_D * (double)t / 16.0;
        tw16[t] = make_float2((float)cos(a), (float)sin(a));
    }
    __syncthreads();

    const int cl = t & 31;
    const int k0c = t >> 5;                  // class index (like h0)

    // ---- Stage A ----
    #pragma unroll
    for (int cc = 0; cc < 2; cc++) {
        const int ch = cl + 32 * cc;
        float2 yv[16];
        #pragma unroll
        for (int k1 = 0; k1 < 16; k1++) yv[k1] = sz[((k1 << 3) + k0c) * 64 + ch];
        #pragma unroll
        for (int m = 0; m < 8; m++) {
            float2 E = make_float2(0.f, 0.f), O = make_float2(0.f, 0.f);
            int ph = 0; const int st = (2 * m) & 15;
            #pragma unroll
            for (int u = 0; u < 8; u++) {
                float2 tt = tw16[ph];
                float2 a = yv[2 * u], bv = yv[2 * u + 1];
                E.x += a.x * tt.x - a.y * tt.y;   E.y += a.x * tt.y + a.y * tt.x;
                O.x += bv.x * tt.x - bv.y * tt.y; O.y += bv.x * tt.y + bv.y * tt.x;
                ph = (ph + st) & 15;
            }
            float2 wm = tw16[m];
            float wOx = wm.x * O.x - wm.y * O.y;
            float wOy = wm.x * O.y + wm.y * O.x;
            sz[((m << 3) + k0c) * 64 + ch]       = make_float2(E.x + wOx, E.y + wOy);
            sz[(((m + 8) << 3) + k0c) * 64 + ch] = make_float2(E.x - wOx, E.y - wOy);
        }
    }
    __syncthreads();

    // ---- Stage B: real part only, pairs (w, w+64) ----
    const int wq = k0c;
    const float inv = 1.0f / 128.0f;
    float* op = out + (size_t)bh * WW * CC + cb;
    #pragma unroll
    for (int j = 0; j < 8; j++) {
        const int w = wq + 8 * j;            // 0..63
        const int m = w & 15;
        #pragma unroll
        for (int cc = 0; cc < 2; cc++) {
            const int ch = cl + 32 * cc;
            float e = 0.f, o = 0.f;
            int ph = 0;
            #pragma unroll
            for (int p = 0; p < 8; p++) {
                float2 tt = tw[ph];
                float2 g = sz[((m << 3) + p) * 64 + ch];
                float re = g.x * tt.x - g.y * tt.y;
                if ((p & 1) == 0) e += re; else o += re;
                ph = (ph + w) & 127;
            }
            op[(size_t)w * CC + ch]        = (e + o) * inv;
            op[(size_t)(w + 64) * CC + ch] = (e - o) * inv;
        }
    }
}

// ---------------------------------------------------------------------------
extern "C" void kernel_launch(void* const* d_in, const int* in_sizes, int n_in,
                              void* d_out, int out_size) {
    const float* x  = (const float*)d_in[0];
    const float* w1 = (const float*)d_in[1];
    const float* b1 = (const float*)d_in[2];
    const float* w2 = (const float*)d_in[3];
    const float* b2 = (const float*)d_in[4];
    float* out = (float*)d_out;

    const int smem_rfft  = 8192 * 4 + 512 * 4 + 128 * 8 + 16 * 8;    // 36000
    const int smem_ffth  = 8192 * 8 + 128 * 8 + 16 * 8;              // 66688
    const int smem_mlp   = 4 * 9216 * 4 + 2 * TM * 97 * 8 + 384 * 4; // 211072
    const int smem_irfft = 8192 * 8 + 128 * 8 + 16 * 8;              // 66688
    cudaFuncSetAttribute(k_rfft_w,  cudaFuncAttributeMaxDynamicSharedMemorySize, smem_rfft);
    cudaFuncSetAttribute(k_fft_h,   cudaFuncAttributeMaxDynamicSharedMemorySize, smem_ffth);
    cudaFuncSetAttribute(k_mlp,     cudaFuncAttributeMaxDynamicSharedMemorySize, smem_mlp);
    cudaFuncSetAttribute(k_irfft_w, cudaFuncAttributeMaxDynamicSharedMemorySize, smem_irfft);

    dim3 g1(BB * HH, CC / 64);           // (512, 12)
    k_rfft_w<<<g1, 256, smem_rfft>>>(x);

    dim3 g2(BB * WF, CC / 64);           // (260, 12)
    k_fft_h<<<g2, 256, smem_ffth>>>(-1.0f, 1.0f / 128.0f);

    dim3 g3((BB * HH * WF) / TM, NB);    // (832, 8)
    k_mlp<<<g3, 320, smem_mlp>>>(w1, b1, w2, b2);

    k_fft_h<<<g2, 256, smem_ffth>>>(+1.0f, 1.0f);

    k_irfft_w<<<g1, 256, smem_irfft>>>(out);
}

// round 5
// speedup vs baseline: 2.3232x; 1.3789x over previous
#include <cuda_runtime.h>
#include <cuda_bf16.h>
#include <math.h>
#include <stdint.h>

#define BB 4
#define HH 128
#define WW 128
#define CC 768
#define WF 65            // WW/2 + 1
#define NB 8
#define PI_D 3.14159265358979323846

// Spectrum scratch, interleaved complex: [B, H, WF, C] float2 (~204MB)
#define NSPEC (BB * HH * WF * CC)
__device__ float2 g_Y[NSPEC];

// Transposed+padded bf16 weight images: [2 layers][8 n][2 parts(hi/lo)][192 nn][200 k]
#define WROW 200
__device__ __nv_bfloat16 g_Wt[2 * 8 * 2 * 192 * WROW];

__device__ __forceinline__ float gelu_exact(float x) {
    return 0.5f * x * (1.0f + erff(x * 0.7071067811865476f));
}
__device__ __forceinline__ float sshrink(float v) {
    float a = fabsf(v) - 0.01f;
    return a > 0.0f ? copysignf(a, v) : 0.0f;
}
__device__ __forceinline__ uint32_t pack_bf2(float a, float b) {
    __nv_bfloat162 p = make_bfloat162(__float2bfloat16(a), __float2bfloat16(b));
    return *(uint32_t*)&p;
}
__device__ __forceinline__ float lo_part(float v) {
    return v - __bfloat162float(__float2bfloat16(v));
}

// m16n8k16 row.col bf16 -> f32 accumulate
__device__ __forceinline__ void mma16816(float* c, const uint32_t* a,
                                         uint32_t b0, uint32_t b1) {
    asm volatile(
        "mma.sync.aligned.m16n8k16.row.col.f32.bf16.bf16.f32 "
        "{%0,%1,%2,%3}, {%4,%5,%6,%7}, {%8,%9}, {%0,%1,%2,%3};"
        : "+f"(c[0]), "+f"(c[1]), "+f"(c[2]), "+f"(c[3])
        : "r"(a[0]), "r"(a[1]), "r"(a[2]), "r"(a[3]), "r"(b0), "r"(b1));
}

// ===========================================================================
// K0: weight prep. B'[nn][k]: for nn<96: k=2i -> wr[i][nn], k=2i+1 -> -wi[i][nn]
//                  for nn>=96 (o=nn-96): k=2i -> wi[i][o], k=2i+1 -> wr[i][o]
// hi/lo bf16 split into parts 0/1; rows padded to WROW (pad zeroed).
// ===========================================================================
__global__ __launch_bounds__(256) void k_prep(const float* __restrict__ w1,
                                              const float* __restrict__ w2) {
    int gid = blockIdx.x * 256 + threadIdx.x;        // 2*8*192*200 = 614400
    if (gid >= 2 * 8 * 192 * WROW) return;
    int k = gid % WROW;
    int nn = (gid / WROW) % 192;
    int n = (gid / (WROW * 192)) % 8;
    int l = gid / (WROW * 192 * 8);
    float v = 0.f;
    if (k < 192) {
        const float* W = l ? w2 : w1;
        int i = k >> 1, odd = k & 1;
        if (nn < 96) {
            v = odd ? -W[73728 + n * 9216 + i * 96 + nn]
                    :  W[n * 9216 + i * 96 + nn];
        } else {
            int o = nn - 96;
            v = odd ? W[n * 9216 + i * 96 + o]
                    : W[73728 + n * 9216 + i * 96 + o];
        }
    }
    float hi = __bfloat162float(__float2bfloat16(v));
    size_t base = ((size_t)(l * 8 + n) * 2) * 192 * WROW + nn * WROW + k;
    g_Wt[base]               = __float2bfloat16(v);
    g_Wt[base + 192 * WROW]  = __float2bfloat16(v - hi);
}

// ===========================================================================
// K3: warp-MMA block-diagonal complex MLP (both layers), IN PLACE on g_Y.
// grid=(260, 8), 256 threads (8 warps: wm=wid%4 rows, wn=wid/4 col-half).
// A = [128][200] bf16 (hi and lo), B = [192][200] bf16 streamed hi then lo.
// C[m][nn] = sum_k A[m][k] B'[nn][k]; 3 terms AhBh + AlBh + AhBl.
// ===========================================================================
#define AH_OFF 0
#define AL_OFF 51200
#define B_OFF  102400
#define BIAS_OFF 179200
#define SMEM_MLP 180736

__global__ __launch_bounds__(256, 1) void k_mlp_mma(const float* __restrict__ b1,
                                                    const float* __restrict__ b2) {
    extern __shared__ __align__(16) char smem[];
    const int t = threadIdx.x;
    const int wid = t >> 5, lane = t & 31;
    const int l4 = lane >> 2, qq = lane & 3;
    const int wm = wid & 3, wn = wid >> 2;
    const int n = blockIdx.y;
    const size_t pbase = (size_t)blockIdx.x * 128;
    const int cb = n * 96;

    float* sbias = (float*)(smem + BIAS_OFF);
    if (t < 96) {
        sbias[t]       = b1[cb + t];
        sbias[96 + t]  = b1[768 + cb + t];
        sbias[192 + t] = b2[cb + t];
        sbias[288 + t] = b2[768 + cb + t];
    }

    // ---- load + convert A tile ----
    for (int idx = t; idx < 128 * 96; idx += 256) {
        int m = idx / 96, i = idx - m * 96;
        float2 y = g_Y[(pbase + m) * CC + cb + i];
        *(uint32_t*)(smem + AH_OFF + (m * WROW + 2 * i) * 2) = pack_bf2(y.x, y.y);
        *(uint32_t*)(smem + AL_OFF + (m * WROW + 2 * i) * 2) =
            pack_bf2(lo_part(y.x), lo_part(y.y));
    }
    __syncthreads();

    float c[2][12][4];
    #pragma unroll
    for (int mf = 0; mf < 2; mf++)
        #pragma unroll
        for (int nf = 0; nf < 12; nf++)
            #pragma unroll
            for (int e = 0; e < 4; e++) c[mf][nf][e] = 0.f;

    const int rb = 32 * wm;
    const int nbase = 96 * wn;

    #pragma unroll 1
    for (int layer = 0; layer < 2; layer++) {
        #pragma unroll 1
        for (int part = 0; part < 2; part++) {
            // stream B part into smem
            {
                const uint4* src = (const uint4*)(g_Wt +
                    ((size_t)(layer * 8 + n) * 2 + part) * 192 * WROW);
                uint4* dst = (uint4*)(smem + B_OFF);
                #pragma unroll 1
                for (int v = t; v < 4800; v += 256) dst[v] = src[v];
            }
            __syncthreads();

            const int nterms = (part == 0) ? 2 : 1;
            #pragma unroll 1
            for (int term = 0; term < nterms; term++) {
                const char* Ab = smem + ((part == 0 && term == 1) ? AL_OFF : AH_OFF);
                #pragma unroll 1
                for (int ks = 0; ks < 12; ks++) {
                    const int k0 = ks * 16;
                    uint32_t a[2][4];
                    #pragma unroll
                    for (int mf = 0; mf < 2; mf++) {
                        const char* ar = Ab + ((rb + 16 * mf + l4) * WROW + k0 + 2 * qq) * 2;
                        a[mf][0] = *(const uint32_t*)ar;
                        a[mf][1] = *(const uint32_t*)(ar + 8 * WROW * 2);
                        a[mf][2] = *(const uint32_t*)(ar + 16);
                        a[mf][3] = *(const uint32_t*)(ar + 8 * WROW * 2 + 16);
                    }
                    #pragma unroll
                    for (int nf = 0; nf < 12; nf++) {
                        const char* br = smem + B_OFF +
                            ((nbase + 8 * nf + l4) * WROW + k0 + 2 * qq) * 2;
                        uint32_t b0 = *(const uint32_t*)br;
                        uint32_t b1 = *(const uint32_t*)(br + 16);
                        mma16816(c[0][nf], a[0], b0, b1);
                        mma16816(c[1][nf], a[1], b0, b1);
                    }
                }
            }
            __syncthreads();   // everyone done reading sA/sB this part
        }

        if (layer == 0) {
            // epilogue 1: bias + GELU, re-split hi/lo back into sA (k-interleaved)
            #pragma unroll
            for (int mf = 0; mf < 2; mf++) {
                const int r0 = rb + 16 * mf + l4;
                #pragma unroll
                for (int nf = 0; nf < 12; nf++) {
                    const int n0 = nbase + 8 * nf + 2 * qq;
                    #pragma unroll
                    for (int e = 0; e < 4; e++) {
                        const int nc = n0 + (e & 1);
                        const int r = (e < 2) ? r0 : r0 + 8;
                        const int kk = wn ? 2 * (nc - 96) + 1 : 2 * nc;
                        float g = gelu_exact(c[mf][nf][e] + sbias[nc]);
                        *(__nv_bfloat16*)(smem + AH_OFF + (r * WROW + kk) * 2) =
                            __float2bfloat16(g);
                        *(__nv_bfloat16*)(smem + AL_OFF + (r * WROW + kk) * 2) =
                            __float2bfloat16(lo_part(g));
                        c[mf][nf][e] = 0.f;
                    }
                }
            }
            __syncthreads();
        } else {
            // epilogue 2: bias + softshrink -> g_Y (scalar float stores)
            float* gY = (float*)g_Y;
            #pragma unroll
            for (int mf = 0; mf < 2; mf++) {
                const int r0 = rb + 16 * mf + l4;
                #pragma unroll
                for (int nf = 0; nf < 12; nf++) {
                    const int n0 = nbase + 8 * nf + 2 * qq;
                    #pragma unroll
                    for (int e = 0; e < 4; e++) {
                        const int nc = n0 + (e & 1);
                        const int r = (e < 2) ? r0 : r0 + 8;
                        float v = sshrink(c[mf][nf][e] + sbias[192 + nc]);
                        size_t gi = ((pbase + r) * CC + cb + (wn ? nc - 96 : nc)) * 2 + wn;
                        gY[gi] = v;
                    }
                }
            }
        }
    }
}

// ===========================================================================
// K1: real FFT along W (four-step: w = 8*w1 + w0). (unchanged from R3)
// ===========================================================================
__global__ __launch_bounds__(256) void k_rfft_w(const float* __restrict__ x) {
    extern __shared__ float sm1[];
    float* sx = sm1;                         // 128 w * 64 c floats
    float* sg8 = sx + 8192;                  // 8 w0 * 64 c (real G[.,8])
    float2* tw = (float2*)(sg8 + 512);       // 128
    float2* tw16 = tw + 128;                 // 16

    const int t = threadIdx.x;
    const int bh = blockIdx.x;
    const int cb = blockIdx.y * 64;

    const float* xp = x + (size_t)bh * WW * CC + cb;
    for (int v = t; v < 128 * 16; v += 256) {
        int w = v >> 4, c4 = v & 15;
        ((float4*)(sx + w * 64))[c4] = ((const float4*)(xp + (size_t)w * CC))[c4];
    }
    if (t < 128) {
        double a = -2.0 * PI_D * (double)t / 128.0;
        tw[t] = make_float2((float)cos(a), (float)sin(a));
    }
    if (t < 16) {
        double a = -2.0 * PI_D * (double)t / 16.0;
        tw16[t] = make_float2((float)cos(a), (float)sin(a));
    }
    __syncthreads();

    const int cl = t & 31;
    const int w0 = t >> 5;

    #pragma unroll
    for (int cc = 0; cc < 2; cc++) {
        const int ch = cl + 32 * cc;
        float xv[16];
        #pragma unroll
        for (int w1 = 0; w1 < 16; w1++) xv[w1] = sx[((w1 << 3) + w0) * 64 + ch];
        #pragma unroll
        for (int m = 0; m < 8; m++) {
            float2 E = make_float2(0.f, 0.f), O = make_float2(0.f, 0.f);
            int ph = 0; const int st = (2 * m) & 15;
            #pragma unroll
            for (int u = 0; u < 8; u++) {
                float2 tt = tw16[ph];
                E.x += xv[2 * u] * tt.x;     E.y += xv[2 * u] * tt.y;
                O.x += xv[2 * u + 1] * tt.x; O.y += xv[2 * u + 1] * tt.y;
                ph = (ph + st) & 15;
            }
            if (m == 0) sg8[w0 * 64 + ch] = E.x - O.x;
            float2 wm = tw16[m];
            float wOx = wm.x * O.x - wm.y * O.y;
            float wOy = wm.x * O.y + wm.y * O.x;
            sx[((m << 3) + w0) * 64 + ch]       = E.x + wOx;
            sx[(((m + 8) << 3) + w0) * 64 + ch] = E.y + wOy;
        }
    }
    __syncthreads();

    const int kq = w0;
    float2* yout = g_Y + (size_t)bh * WF * CC + cb;
    const int jmax = (kq == 0) ? 9 : 8;
    for (int j = 0; j < jmax; j++) {
        const int k = kq + 8 * j;
        const int k0 = k & 15;
        const bool is8 = (k0 == 8);
        const int k0p = (k0 <= 8) ? k0 : 16 - k0;
        const float si = (k0 <= 8) ? 1.f : -1.f;
        #pragma unroll
        for (int cc = 0; cc < 2; cc++) {
            const int ch = cl + 32 * cc;
            float ax = 0.f, ay = 0.f;
            int ph = 0;
            #pragma unroll
            for (int p = 0; p < 8; p++) {
                float2 tt = tw[ph];
                float gre, gim;
                if (is8) { gre = sg8[p * 64 + ch]; gim = 0.f; }
                else {
                    gre = sx[((k0p << 3) + p) * 64 + ch];
                    gim = si * sx[(((k0p + 8) << 3) + p) * 64 + ch];
                }
                ax += gre * tt.x - gim * tt.y;
                ay += gre * tt.y + gim * tt.x;
                ph = (ph + k) & 127;
            }
            yout[(size_t)k * CC + ch] = make_float2(ax, ay);
        }
    }
}

// ===========================================================================
// K2/K4: complex FFT along H (four-step), IN PLACE. (unchanged from R3)
// ===========================================================================
__global__ __launch_bounds__(256) void k_fft_h(float sgn, float scale) {
    extern __shared__ float sm2[];
    float2* sy = (float2*)sm2;               // 128 h * 64 c
    float2* tw = sy + 8192;
    float2* tw16 = tw + 128;

    const int t = threadIdx.x;
    const int b  = blockIdx.x / WF;
    const int kw = blockIdx.x % WF;
    const int cb = blockIdx.y * 64;
    const size_t base = ((size_t)b * HH * WF + kw) * CC + cb;
    const size_t sh = (size_t)WF * CC;

    for (int idx = t; idx < 8192; idx += 256) {
        int h = idx >> 6, c = idx & 63;
        sy[idx] = g_Y[base + (size_t)h * sh + c];
    }
    if (t < 128) {
        double a = sgn * 2.0 * PI_D * (double)t / 128.0;
        tw[t] = make_float2((float)cos(a), (float)sin(a));
    }
    if (t < 16) {
        double a = sgn * 2.0 * PI_D * (double)t / 16.0;
        tw16[t] = make_float2((float)cos(a), (float)sin(a));
    }
    __syncthreads();

    const int cl = t & 31;
    const int h0 = t >> 5;

    #pragma unroll
    for (int cc = 0; cc < 2; cc++) {
        const int ch = cl + 32 * cc;
        float2 yv[16];
        #pragma unroll
        for (int h1 = 0; h1 < 16; h1++) yv[h1] = sy[((h1 << 3) + h0) * 64 + ch];
        #pragma unroll
        for (int m = 0; m < 8; m++) {
            float2 E = make_float2(0.f, 0.f), O = make_float2(0.f, 0.f);
            int ph = 0; const int st = (2 * m) & 15;
            #pragma unroll
            for (int u = 0; u < 8; u++) {
                float2 tt = tw16[ph];
                float2 a = yv[2 * u], bv = yv[2 * u + 1];
                E.x += a.x * tt.x - a.y * tt.y;   E.y += a.x * tt.y + a.y * tt.x;
                O.x += bv.x * tt.x - bv.y * tt.y; O.y += bv.x * tt.y + bv.y * tt.x;
                ph = (ph + st) & 15;
            }
            float2 wm = tw16[m];
            float wOx = wm.x * O.x - wm.y * O.y;
            float wOy = wm.x * O.y + wm.y * O.x;
            sy[((m << 3) + h0) * 64 + ch]       = make_float2(E.x + wOx, E.y + wOy);
            sy[(((m + 8) << 3) + h0) * 64 + ch] = make_float2(E.x - wOx, E.y - wOy);
        }
    }
    __syncthreads();

    const int kq = h0;
    #pragma unroll
    for (int j = 0; j < 8; j++) {
        const int k = kq + 8 * j;
        const int k0 = k & 15;
        #pragma unroll
        for (int cc = 0; cc < 2; cc++) {
            const int ch = cl + 32 * cc;
            float Ex = 0.f, Ey = 0.f, Ox = 0.f, Oy = 0.f;
            int ph = 0;
            #pragma unroll
            for (int p = 0; p < 8; p++) {
                float2 tt = tw[ph];
                float2 g = sy[((k0 << 3) + p) * 64 + ch];
                float rx = g.x * tt.x - g.y * tt.y;
                float ry = g.x * tt.y + g.y * tt.x;
                if ((p & 1) == 0) { Ex += rx; Ey += ry; }
                else              { Ox += rx; Oy += ry; }
                ph = (ph + k) & 127;
            }
            g_Y[base + (size_t)k * sh + ch] =
                make_float2((Ex + Ox) * scale, (Ey + Oy) * scale);
            g_Y[base + (size_t)(k + 64) * sh + ch] =
                make_float2((Ex - Ox) * scale, (Ey - Oy) * scale);
        }
    }
}

// ===========================================================================
// K5: inverse real FFT along W (four-step). (unchanged from R3)
// ===========================================================================
__global__ __launch_bounds__(256) void k_irfft_w(float* __restrict__ out) {
    extern __shared__ float sm5[];
    float2* sz = (float2*)sm5;               // 128 k * 64 c
    float2* tw = sz + 8192;
    float2* tw16 = tw + 128;

    const int t = threadIdx.x;
    const int bh = blockIdx.x;
    const int cb = blockIdx.y * 64;
    const size_t base = (size_t)bh * WF * CC + cb;

    for (int idx = t; idx < 8192; idx += 256) {
        int k = idx >> 6, c = idx & 63;
        if (k <= 64) {
            sz[idx] = g_Y[base + (size_t)k * CC + c];
        } else {
            float2 v = g_Y[base + (size_t)(128 - k) * CC + c];
            sz[idx] = make_float2(v.x, -v.y);
        }
    }
    if (t < 128) {
        double a = 2.0 * PI_D * (double)t / 128.0;
        tw[t] = make_float2((float)cos(a), (float)sin(a));
    }
    if (t < 16) {
        double a = 2.0 * PI_D * (double)t / 16.0;
        tw16[t] = make_float2((float)cos(a), (float)sin(a));
    }
    __syncthreads();

    const int cl = t & 31;
    const int k0c = t >> 5;

    #pragma unroll
    for (int cc = 0; cc < 2; cc++) {
        const int ch = cl + 32 * cc;
        float2 yv[16];
        #pragma unroll
        for (int k1 = 0; k1 < 16; k1++) yv[k1] = sz[((k1 << 3) + k0c) * 64 + ch];
        #pragma unroll
        for (int m = 0; m < 8; m++) {
            float2 E = make_float2(0.f, 0.f), O = make_float2(0.f, 0.f);
            int ph = 0; const int st = (2 * m) & 15;
            #pragma unroll
            for (int u = 0; u < 8; u++) {
                float2 tt = tw16[ph];
                float2 a = yv[2 * u], bv = yv[2 * u + 1];
                E.x += a.x * tt.x - a.y * tt.y;   E.y += a.x * tt.y + a.y * tt.x;
                O.x += bv.x * tt.x - bv.y * tt.y; O.y += bv.x * tt.y + bv.y * tt.x;
                ph = (ph + st) & 15;
            }
            float2 wm = tw16[m];
            float wOx = wm.x * O.x - wm.y * O.y;
            float wOy = wm.x * O.y + wm.y * O.x;
            sz[((m << 3) + k0c) * 64 + ch]       = make_float2(E.x + wOx, E.y + wOy);
            sz[(((m + 8) << 3) + k0c) * 64 + ch] = make_float2(E.x - wOx, E.y - wOy);
        }
    }
    __syncthreads();

    const int wq = k0c;
    const float inv = 1.0f / 128.0f;
    float* op = out + (size_t)bh * WW * CC + cb;
    #pragma unroll
    for (int j = 0; j < 8; j++) {
        const int w = wq + 8 * j;
        const int m = w & 15;
        #pragma unroll
        for (int cc = 0; cc < 2; cc++) {
            const int ch = cl + 32 * cc;
            float e = 0.f, o = 0.f;
            int ph = 0;
            #pragma unroll
            for (int p = 0; p < 8; p++) {
                float2 tt = tw[ph];
                float2 g = sz[((m << 3) + p) * 64 + ch];
                float re = g.x * tt.x - g.y * tt.y;
                if ((p & 1) == 0) e += re; else o += re;
                ph = (ph + w) & 127;
            }
            op[(size_t)w * CC + ch]        = (e + o) * inv;
            op[(size_t)(w + 64) * CC + ch] = (e - o) * inv;
        }
    }
}

// ---------------------------------------------------------------------------
extern "C" void kernel_launch(void* const* d_in, const int* in_sizes, int n_in,
                              void* d_out, int out_size) {
    const float* x  = (const float*)d_in[0];
    const float* w1 = (const float*)d_in[1];
    const float* b1 = (const float*)d_in[2];
    const float* w2 = (const float*)d_in[3];
    const float* b2 = (const float*)d_in[4];
    float* out = (float*)d_out;

    const int smem_rfft  = 8192 * 4 + 512 * 4 + 128 * 8 + 16 * 8;
    const int smem_ffth  = 8192 * 8 + 128 * 8 + 16 * 8;
    const int smem_irfft = 8192 * 8 + 128 * 8 + 16 * 8;
    cudaFuncSetAttribute(k_rfft_w,  cudaFuncAttributeMaxDynamicSharedMemorySize, smem_rfft);
    cudaFuncSetAttribute(k_fft_h,   cudaFuncAttributeMaxDynamicSharedMemorySize, smem_ffth);
    cudaFuncSetAttribute(k_mlp_mma, cudaFuncAttributeMaxDynamicSharedMemorySize, SMEM_MLP);
    cudaFuncSetAttribute(k_irfft_w, cudaFuncAttributeMaxDynamicSharedMemorySize, smem_irfft);

    k_prep<<<2400, 256>>>(w1, w2);

    dim3 g1(BB * HH, CC / 64);           // (512, 12)
    k_rfft_w<<<g1, 256, smem_rfft>>>(x);

    dim3 g2(BB * WF, CC / 64);           // (260, 12)
    k_fft_h<<<g2, 256, smem_ffth>>>(-1.0f, 1.0f / 128.0f);

    dim3 g3(260, NB);                    // 33280/128 = 260 m-tiles
    k_mlp_mma<<<g3, 256, SMEM_MLP>>>(b1, b2);

    k_fft_h<<<g2, 256, smem_ffth>>>(+1.0f, 1.0f);

    k_irfft_w<<<g1, 256, smem_irfft>>>(out);
}

// round 6
// speedup vs baseline: 2.9544x; 1.2717x over previous
#include <cuda_runtime.h>
#include <cuda_bf16.h>
#include <math.h>
#include <stdint.h>

#define BB 4
#define HH 128
#define WW 128
#define CC 768
#define WF 65            // WW/2 + 1
#define NB 8
#define PI_D 3.14159265358979323846

// Spectrum scratch, interleaved complex: [B, H, WF, C] float2 (~204MB)
#define NSPEC (BB * HH * WF * CC)
__device__ float2 g_Y[NSPEC];

// Chunk-major bf16 weight images:
// [2 layers][8 n][2 parts(hi/lo)][4 chunks][192 rows][56 cols(48 used)]
#define BROW 56
#define CHUNK_ELEM (192 * BROW)           // 10752 elems = 21504 B
__device__ __align__(16) __nv_bfloat16 g_Wt[2 * 8 * 2 * 4 * CHUNK_ELEM];

__device__ __forceinline__ float gelu_exact(float x) {
    return 0.5f * x * (1.0f + erff(x * 0.7071067811865476f));
}
__device__ __forceinline__ float sshrink(float v) {
    float a = fabsf(v) - 0.01f;
    return a > 0.0f ? copysignf(a, v) : 0.0f;
}
__device__ __forceinline__ uint32_t pack_bf2(float a, float b) {
    __nv_bfloat162 p = make_bfloat162(__float2bfloat16(a), __float2bfloat16(b));
    return *(uint32_t*)&p;
}
__device__ __forceinline__ float lo_part(float v) {
    return v - __bfloat162float(__float2bfloat16(v));
}
__device__ __forceinline__ uint32_t smem_u32(const void* p) {
    uint32_t a;
    asm("{ .reg .u64 t; cvta.to.shared.u64 t, %1; cvt.u32.u64 %0, t; }"
        : "=r"(a) : "l"(p));
    return a;
}
__device__ __forceinline__ void cp16(uint32_t dst, const void* src) {
    asm volatile("cp.async.cg.shared.global [%0], [%1], 16;" :: "r"(dst), "l"(src));
}
__device__ __forceinline__ void cp_commit() {
    asm volatile("cp.async.commit_group;" ::: "memory");
}
__device__ __forceinline__ void cp_wait0() {
    asm volatile("cp.async.wait_group 0;" ::: "memory");
}

// m16n8k16 row.col bf16 -> f32 accumulate
__device__ __forceinline__ void mma16816(float* c, const uint32_t* a,
                                         uint32_t b0, uint32_t b1) {
    asm volatile(
        "mma.sync.aligned.m16n8k16.row.col.f32.bf16.bf16.f32 "
        "{%0,%1,%2,%3}, {%4,%5,%6,%7}, {%8,%9}, {%0,%1,%2,%3};"
        : "+f"(c[0]), "+f"(c[1]), "+f"(c[2]), "+f"(c[3])
        : "r"(a[0]), "r"(a[1]), "r"(a[2]), "r"(a[3]), "r"(b0), "r"(b1));
}

// ===========================================================================
// K0: weight prep -> chunk-major layout.
// B'[nn][k]: nn<96: k=2i -> wr[i][nn], k=2i+1 -> -wi[i][nn]
//            nn>=96 (o=nn-96): k=2i -> wi[i][o], k=2i+1 -> wr[i][o]
// ===========================================================================
__global__ __launch_bounds__(256) void k_prep(const float* __restrict__ w1,
                                              const float* __restrict__ w2) {
    int gid = blockIdx.x * 256 + threadIdx.x;    // 2*8*2*4*192*56 = 1376256
    if (gid >= 2 * 8 * 2 * 4 * CHUNK_ELEM) return;
    int kc = gid % BROW;
    int nn = (gid / BROW) % 192;
    int ck = (gid / CHUNK_ELEM) % 4;
    int part = (gid / (CHUNK_ELEM * 4)) % 2;
    int n = (gid / (CHUNK_ELEM * 8)) % 8;
    int l = gid / (CHUNK_ELEM * 64);
    float v = 0.f;
    if (kc < 48) {
        int k = ck * 48 + kc;
        const float* W = l ? w2 : w1;
        int i = k >> 1, odd = k & 1;
        if (nn < 96) {
            v = odd ? -W[73728 + n * 9216 + i * 96 + nn]
                    :  W[n * 9216 + i * 96 + nn];
        } else {
            int o = nn - 96;
            v = odd ? W[n * 9216 + i * 96 + o]
                    : W[73728 + n * 9216 + i * 96 + o];
        }
    }
    if (part) v = lo_part(v);
    g_Wt[gid] = __float2bfloat16(v);
}

// ===========================================================================
// K3: warp-MMA complex MLP (both layers), IN PLACE on g_Y.
// grid=(520, 8), 256 thr, 2 CTAs/SM. M=64 rows/CTA.
// 8 warps: wm=wid&1 (2 x 32 rows), wn=wid>>1 (4 x 48 cols of N=192).
// B streamed as 16 chunks (2 layers x 2 parts x 4 k-chunks), cp.async 2-buf.
// ===========================================================================
#define WROW 200
#define AH_OFF 0
#define AL_OFF 25600
#define B_OFF  51200
#define BIAS_OFF 94208
#define SMEM_MLP 95744

__global__ __launch_bounds__(256, 2) void k_mlp_mma(const float* __restrict__ b1,
                                                    const float* __restrict__ b2) {
    extern __shared__ __align__(16) char smem[];
    const int t = threadIdx.x;
    const int wid = t >> 5, lane = t & 31;
    const int l4 = lane >> 2, qq = lane & 3;
    const int wm = wid & 1, wn = wid >> 1;
    const int n = blockIdx.y;
    const size_t pbase = (size_t)blockIdx.x * 64;
    const int cb = n * 96;
    const uint32_t sb = smem_u32(smem);

    const __nv_bfloat16* wbase = g_Wt + (size_t)(blockIdx.y * 2) * 4 * CHUNK_ELEM
                               + (size_t)0;   // offset by (l*8+n)*2*4*CHUNK below

    // issue chunk 0 load immediately (layer0, part0, ck0)
    {
        const char* src = (const char*)(g_Wt + (size_t)n * 2 * 4 * CHUNK_ELEM);
        uint32_t dst = sb + B_OFF;
        for (int v = t; v < 1344; v += 256) cp16(dst + v * 16, src + v * 16);
        cp_commit();
    }

    float* sbias = (float*)(smem + BIAS_OFF);
    if (t < 96) {
        sbias[t]       = b1[cb + t];
        sbias[96 + t]  = b1[768 + cb + t];
        sbias[192 + t] = b2[cb + t];
        sbias[288 + t] = b2[768 + cb + t];
    }

    // ---- load + convert A tile (64 rows) ----
    for (int idx = t; idx < 64 * 96; idx += 256) {
        int m = idx / 96, i = idx - m * 96;
        float2 y = g_Y[(pbase + m) * CC + cb + i];
        *(uint32_t*)(smem + AH_OFF + (m * WROW + 2 * i) * 2) = pack_bf2(y.x, y.y);
        *(uint32_t*)(smem + AL_OFF + (m * WROW + 2 * i) * 2) =
            pack_bf2(lo_part(y.x), lo_part(y.y));
    }

    float c[2][6][4];
    #pragma unroll
    for (int mf = 0; mf < 2; mf++)
        #pragma unroll
        for (int nf = 0; nf < 6; nf++)
            #pragma unroll
            for (int e = 0; e < 4; e++) c[mf][nf][e] = 0.f;

    const int rb = 32 * wm;
    const int nbase = 48 * wn;

    #pragma unroll 1
    for (int cid = 0; cid < 16; cid++) {
        cp_wait0();
        __syncthreads();
        if (cid < 15) {
            int nx = cid + 1;
            int l = nx >> 3, part = (nx >> 2) & 1, ck = nx & 3;
            const char* src = (const char*)(g_Wt +
                ((size_t)((l * 8 + n) * 2 + part) * 4 + ck) * CHUNK_ELEM);
            uint32_t dst = sb + B_OFF + (nx & 1) * 21504;
            #pragma unroll 1
            for (int v = t; v < 1344; v += 256) cp16(dst + v * 16, src + v * 16);
            cp_commit();
        }
        if (cid == 8) {
            // ---- epilogue 1: bias+GELU, rewrite A (hi/lo), reset accum ----
            #pragma unroll
            for (int mf = 0; mf < 2; mf++) {
                const int r0 = rb + 16 * mf + l4;
                #pragma unroll
                for (int nf = 0; nf < 6; nf++) {
                    const int n0 = nbase + 8 * nf + 2 * qq;
                    #pragma unroll
                    for (int e = 0; e < 4; e++) {
                        const int nc = n0 + (e & 1);
                        const int r = (e < 2) ? r0 : r0 + 8;
                        const int kk = (nc < 96) ? 2 * nc : 2 * (nc - 96) + 1;
                        float g = gelu_exact(c[mf][nf][e] + sbias[nc]);
                        *(__nv_bfloat16*)(smem + AH_OFF + (r * WROW + kk) * 2) =
                            __float2bfloat16(g);
                        *(__nv_bfloat16*)(smem + AL_OFF + (r * WROW + kk) * 2) =
                            __float2bfloat16(lo_part(g));
                        c[mf][nf][e] = 0.f;
                    }
                }
            }
            __syncthreads();
        }
        // ---- compute chunk cid ----
        {
            const int part = (cid >> 2) & 1;
            const int ck = cid & 3;
            const char* Bb = smem + B_OFF + (cid & 1) * 21504;
            #pragma unroll
            for (int ksl = 0; ksl < 3; ksl++) {
                const int kl = ksl * 16;
                const int kg = ck * 48 + kl;
                uint32_t ah[2][4], al[2][4];
                #pragma unroll
                for (int mf = 0; mf < 2; mf++) {
                    const int ar = (rb + 16 * mf + l4) * WROW + kg + 2 * qq;
                    ah[mf][0] = *(const uint32_t*)(smem + AH_OFF + ar * 2);
                    ah[mf][1] = *(const uint32_t*)(smem + AH_OFF + (ar + 8 * WROW) * 2);
                    ah[mf][2] = *(const uint32_t*)(smem + AH_OFF + (ar + 8) * 2);
                    ah[mf][3] = *(const uint32_t*)(smem + AH_OFF + (ar + 8 * WROW + 8) * 2);
                    if (part == 0) {
                        al[mf][0] = *(const uint32_t*)(smem + AL_OFF + ar * 2);
                        al[mf][1] = *(const uint32_t*)(smem + AL_OFF + (ar + 8 * WROW) * 2);
                        al[mf][2] = *(const uint32_t*)(smem + AL_OFF + (ar + 8) * 2);
                        al[mf][3] = *(const uint32_t*)(smem + AL_OFF + (ar + 8 * WROW + 8) * 2);
                    }
                }
                #pragma unroll
                for (int nf = 0; nf < 6; nf++) {
                    const int br = (nbase + 8 * nf + l4) * BROW + kl + 2 * qq;
                    uint32_t b0 = *(const uint32_t*)(Bb + br * 2);
                    uint32_t b1 = *(const uint32_t*)(Bb + (br + 8) * 2);
                    mma16816(c[0][nf], ah[0], b0, b1);
                    mma16816(c[1][nf], ah[1], b0, b1);
                    if (part == 0) {
                        mma16816(c[0][nf], al[0], b0, b1);
                        mma16816(c[1][nf], al[1], b0, b1);
                    }
                }
            }
        }
    }

    // ---- epilogue 2: bias + softshrink -> g_Y ----
    float* gY = (float*)g_Y;
    #pragma unroll
    for (int mf = 0; mf < 2; mf++) {
        const int r0 = rb + 16 * mf + l4;
        #pragma unroll
        for (int nf = 0; nf < 6; nf++) {
            const int n0 = nbase + 8 * nf + 2 * qq;
            #pragma unroll
            for (int e = 0; e < 4; e++) {
                const int nc = n0 + (e & 1);
                const int r = (e < 2) ? r0 : r0 + 8;
                float v = sshrink(c[mf][nf][e] + sbias[192 + nc]);
                const int cch = (nc < 96) ? nc : nc - 96;
                size_t gi = ((pbase + r) * CC + cb + cch) * 2 + (nc >= 96);
                gY[gi] = v;
            }
        }
    }
}

// ===========================================================================
// K1: real FFT along W (four-step: w = 8*w1 + w0). (unchanged)
// ===========================================================================
__global__ __launch_bounds__(256) void k_rfft_w(const float* __restrict__ x) {
    extern __shared__ float sm1[];
    float* sx = sm1;
    float* sg8 = sx + 8192;
    float2* tw = (float2*)(sg8 + 512);
    float2* tw16 = tw + 128;

    const int t = threadIdx.x;
    const int bh = blockIdx.x;
    const int cb = blockIdx.y * 64;

    const float* xp = x + (size_t)bh * WW * CC + cb;
    for (int v = t; v < 128 * 16; v += 256) {
        int w = v >> 4, c4 = v & 15;
        ((float4*)(sx + w * 64))[c4] = ((const float4*)(xp + (size_t)w * CC))[c4];
    }
    if (t < 128) {
        double a = -2.0 * PI_D * (double)t / 128.0;
        tw[t] = make_float2((float)cos(a), (float)sin(a));
    }
    if (t < 16) {
        double a = -2.0 * PI_D * (double)t / 16.0;
        tw16[t] = make_float2((float)cos(a), (float)sin(a));
    }
    __syncthreads();

    const int cl = t & 31;
    const int w0 = t >> 5;

    #pragma unroll
    for (int cc = 0; cc < 2; cc++) {
        const int ch = cl + 32 * cc;
        float xv[16];
        #pragma unroll
        for (int w1 = 0; w1 < 16; w1++) xv[w1] = sx[((w1 << 3) + w0) * 64 + ch];
        #pragma unroll
        for (int m = 0; m < 8; m++) {
            float2 E = make_float2(0.f, 0.f), O = make_float2(0.f, 0.f);
            int ph = 0; const int st = (2 * m) & 15;
            #pragma unroll
            for (int u = 0; u < 8; u++) {
                float2 tt = tw16[ph];
                E.x += xv[2 * u] * tt.x;     E.y += xv[2 * u] * tt.y;
                O.x += xv[2 * u + 1] * tt.x; O.y += xv[2 * u + 1] * tt.y;
                ph = (ph + st) & 15;
            }
            if (m == 0) sg8[w0 * 64 + ch] = E.x - O.x;
            float2 wm = tw16[m];
            float wOx = wm.x * O.x - wm.y * O.y;
            float wOy = wm.x * O.y + wm.y * O.x;
            sx[((m << 3) + w0) * 64 + ch]       = E.x + wOx;
            sx[(((m + 8) << 3) + w0) * 64 + ch] = E.y + wOy;
        }
    }
    __syncthreads();

    const int kq = w0;
    float2* yout = g_Y + (size_t)bh * WF * CC + cb;
    const int jmax = (kq == 0) ? 9 : 8;
    for (int j = 0; j < jmax; j++) {
        const int k = kq + 8 * j;
        const int k0 = k & 15;
        const bool is8 = (k0 == 8);
        const int k0p = (k0 <= 8) ? k0 : 16 - k0;
        const float si = (k0 <= 8) ? 1.f : -1.f;
        #pragma unroll
        for (int cc = 0; cc < 2; cc++) {
            const int ch = cl + 32 * cc;
            float ax = 0.f, ay = 0.f;
            int ph = 0;
            #pragma unroll
            for (int p = 0; p < 8; p++) {
                float2 tt = tw[ph];
                float gre, gim;
                if (is8) { gre = sg8[p * 64 + ch]; gim = 0.f; }
                else {
                    gre = sx[((k0p << 3) + p) * 64 + ch];
                    gim = si * sx[(((k0p + 8) << 3) + p) * 64 + ch];
                }
                ax += gre * tt.x - gim * tt.y;
                ay += gre * tt.y + gim * tt.x;
                ph = (ph + k) & 127;
            }
            yout[(size_t)k * CC + ch] = make_float2(ax, ay);
        }
    }
}

// ===========================================================================
// K2/K4: complex FFT along H (four-step), IN PLACE. (unchanged)
// ===========================================================================
__global__ __launch_bounds__(256) void k_fft_h(float sgn, float scale) {
    extern __shared__ float sm2[];
    float2* sy = (float2*)sm2;
    float2* tw = sy + 8192;
    float2* tw16 = tw + 128;

    const int t = threadIdx.x;
    const int b  = blockIdx.x / WF;
    const int kw = blockIdx.x % WF;
    const int cb = blockIdx.y * 64;
    const size_t base = ((size_t)b * HH * WF + kw) * CC + cb;
    const size_t sh = (size_t)WF * CC;

    for (int idx = t; idx < 8192; idx += 256) {
        int h = idx >> 6, c = idx & 63;
        sy[idx] = g_Y[base + (size_t)h * sh + c];
    }
    if (t < 128) {
        double a = sgn * 2.0 * PI_D * (double)t / 128.0;
        tw[t] = make_float2((float)cos(a), (float)sin(a));
    }
    if (t < 16) {
        double a = sgn * 2.0 * PI_D * (double)t / 16.0;
        tw16[t] = make_float2((float)cos(a), (float)sin(a));
    }
    __syncthreads();

    const int cl = t & 31;
    const int h0 = t >> 5;

    #pragma unroll
    for (int cc = 0; cc < 2; cc++) {
        const int ch = cl + 32 * cc;
        float2 yv[16];
        #pragma unroll
        for (int h1 = 0; h1 < 16; h1++) yv[h1] = sy[((h1 << 3) + h0) * 64 + ch];
        #pragma unroll
        for (int m = 0; m < 8; m++) {
            float2 E = make_float2(0.f, 0.f), O = make_float2(0.f, 0.f);
            int ph = 0; const int st = (2 * m) & 15;
            #pragma unroll
            for (int u = 0; u < 8; u++) {
                float2 tt = tw16[ph];
                float2 a = yv[2 * u], bv = yv[2 * u + 1];
                E.x += a.x * tt.x - a.y * tt.y;   E.y += a.x * tt.y + a.y * tt.x;
                O.x += bv.x * tt.x - bv.y * tt.y; O.y += bv.x * tt.y + bv.y * tt.x;
                ph = (ph + st) & 15;
            }
            float2 wm = tw16[m];
            float wOx = wm.x * O.x - wm.y * O.y;
            float wOy = wm.x * O.y + wm.y * O.x;
            sy[((m << 3) + h0) * 64 + ch]       = make_float2(E.x + wOx, E.y + wOy);
            sy[(((m + 8) << 3) + h0) * 64 + ch] = make_float2(E.x - wOx, E.y - wOy);
        }
    }
    __syncthreads();

    const int kq = h0;
    #pragma unroll
    for (int j = 0; j < 8; j++) {
        const int k = kq + 8 * j;
        const int k0 = k & 15;
        #pragma unroll
        for (int cc = 0; cc < 2; cc++) {
            const int ch = cl + 32 * cc;
            float Ex = 0.f, Ey = 0.f, Ox = 0.f, Oy = 0.f;
            int ph = 0;
            #pragma unroll
            for (int p = 0; p < 8; p++) {
                float2 tt = tw[ph];
                float2 g = sy[((k0 << 3) + p) * 64 + ch];
                float rx = g.x * tt.x - g.y * tt.y;
                float ry = g.x * tt.y + g.y * tt.x;
                if ((p & 1) == 0) { Ex += rx; Ey += ry; }
                else              { Ox += rx; Oy += ry; }
                ph = (ph + k) & 127;
            }
            g_Y[base + (size_t)k * sh + ch] =
                make_float2((Ex + Ox) * scale, (Ey + Oy) * scale);
            g_Y[base + (size_t)(k + 64) * sh + ch] =
                make_float2((Ex - Ox) * scale, (Ey - Oy) * scale);
        }
    }
}

// ===========================================================================
// K5: inverse real FFT along W (four-step). (unchanged)
// ===========================================================================
__global__ __launch_bounds__(256) void k_irfft_w(float* __restrict__ out) {
    extern __shared__ float sm5[];
    float2* sz = (float2*)sm5;
    float2* tw = sz + 8192;
    float2* tw16 = tw + 128;

    const int t = threadIdx.x;
    const int bh = blockIdx.x;
    const int cb = blockIdx.y * 64;
    const size_t base = (size_t)bh * WF * CC + cb;

    for (int idx = t; idx < 8192; idx += 256) {
        int k = idx >> 6, c = idx & 63;
        if (k <= 64) {
            sz[idx] = g_Y[base + (size_t)k * CC + c];
        } else {
            float2 v = g_Y[base + (size_t)(128 - k) * CC + c];
            sz[idx] = make_float2(v.x, -v.y);
        }
    }
    if (t < 128) {
        double a = 2.0 * PI_D * (double)t / 128.0;
        tw[t] = make_float2((float)cos(a), (float)sin(a));
    }
    if (t < 16) {
        double a = 2.0 * PI_D * (double)t / 16.0;
        tw16[t] = make_float2((float)cos(a), (float)sin(a));
    }
    __syncthreads();

    const int cl = t & 31;
    const int k0c = t >> 5;

    #pragma unroll
    for (int cc = 0; cc < 2; cc++) {
        const int ch = cl + 32 * cc;
        float2 yv[16];
        #pragma unroll
        for (int k1 = 0; k1 < 16; k1++) yv[k1] = sz[((k1 << 3) + k0c) * 64 + ch];
        #pragma unroll
        for (int m = 0; m < 8; m++) {
            float2 E = make_float2(0.f, 0.f), O = make_float2(0.f, 0.f);
            int ph = 0; const int st = (2 * m) & 15;
            #pragma unroll
            for (int u = 0; u < 8; u++) {
                float2 tt = tw16[ph];
                float2 a = yv[2 * u], bv = yv[2 * u + 1];
                E.x += a.x * tt.x - a.y * tt.y;   E.y += a.x * tt.y + a.y * tt.x;
                O.x += bv.x * tt.x - bv.y * tt.y; O.y += bv.x * tt.y + bv.y * tt.x;
                ph = (ph + st) & 15;
            }
            float2 wm = tw16[m];
            float wOx = wm.x * O.x - wm.y * O.y;
            float wOy = wm.x * O.y + wm.y * O.x;
            sz[((m << 3) + k0c) * 64 + ch]       = make_float2(E.x + wOx, E.y + wOy);
            sz[(((m + 8) << 3) + k0c) * 64 + ch] = make_float2(E.x - wOx, E.y - wOy);
        }
    }
    __syncthreads();

    const int wq = k0c;
    const float inv = 1.0f / 128.0f;
    float* op = out + (size_t)bh * WW * CC + cb;
    #pragma unroll
    for (int j = 0; j < 8; j++) {
        const int w = wq + 8 * j;
        const int m = w & 15;
        #pragma unroll
        for (int cc = 0; cc < 2; cc++) {
            const int ch = cl + 32 * cc;
            float e = 0.f, o = 0.f;
            int ph = 0;
            #pragma unroll
            for (int p = 0; p < 8; p++) {
                float2 tt = tw[ph];
                float2 g = sz[((m << 3) + p) * 64 + ch];
                float re = g.x * tt.x - g.y * tt.y;
                if ((p & 1) == 0) e += re; else o += re;
                ph = (ph + w) & 127;
            }
            op[(size_t)w * CC + ch]        = (e + o) * inv;
            op[(size_t)(w + 64) * CC + ch] = (e - o) * inv;
        }
    }
}

// ---------------------------------------------------------------------------
extern "C" void kernel_launch(void* const* d_in, const int* in_sizes, int n_in,
                              void* d_out, int out_size) {
    const float* x  = (const float*)d_in[0];
    const float* w1 = (const float*)d_in[1];
    const float* b1 = (const float*)d_in[2];
    const float* w2 = (const float*)d_in[3];
    const float* b2 = (const float*)d_in[4];
    float* out = (float*)d_out;

    const int smem_rfft  = 8192 * 4 + 512 * 4 + 128 * 8 + 16 * 8;
    const int smem_ffth  = 8192 * 8 + 128 * 8 + 16 * 8;
    const int smem_irfft = 8192 * 8 + 128 * 8 + 16 * 8;
    cudaFuncSetAttribute(k_rfft_w,  cudaFuncAttributeMaxDynamicSharedMemorySize, smem_rfft);
    cudaFuncSetAttribute(k_fft_h,   cudaFuncAttributeMaxDynamicSharedMemorySize, smem_ffth);
    cudaFuncSetAttribute(k_mlp_mma, cudaFuncAttributeMaxDynamicSharedMemorySize, SMEM_MLP);
    cudaFuncSetAttribute(k_irfft_w, cudaFuncAttributeMaxDynamicSharedMemorySize, smem_irfft);

    k_prep<<<5376, 256>>>(w1, w2);

    dim3 g1(BB * HH, CC / 64);           // (512, 12)
    k_rfft_w<<<g1, 256, smem_rfft>>>(x);

    dim3 g2(BB * WF, CC / 64);           // (260, 12)
    k_fft_h<<<g2, 256, smem_ffth>>>(-1.0f, 1.0f / 128.0f);

    dim3 g3(520, NB);                    // 33280/64 = 520 m-tiles
    k_mlp_mma<<<g3, 256, SMEM_MLP>>>(b1, b2);

    k_fft_h<<<g2, 256, smem_ffth>>>(+1.0f, 1.0f);

    k_irfft_w<<<g1, 256, smem_irfft>>>(out);
}